// round 10
// baseline (speedup 1.0000x reference)
#include <cuda_runtime.h>
#include <cuda_bf16.h>
#include <math.h>

// ============================================================================
// RNN: h_t = tanh(x_t @ Wi^T + bi + h_{t-1} @ Wh^T + bh)
// Phase 1: bf16 hi/lo split tensor-core GEMM, double-buffered SMEM (2-stage).
// Phase 2: persistent tensor-core recurrence = R7 design (single 128-CTA
//          global barrier, PROVEN) + xi prefetch at step start.
//          (R8's per-row-group drifting barrier reverted: two consecutive
//           container failures implicate it as a hang risk.)
// Shapes hardcoded: L=512, B=128, D=H=1024 (fp32).
// ============================================================================

#define L_    512
#define B_    128
#define H_    1024
#define NCTA  128
#define BLK2  512

typedef unsigned long long ull;
typedef unsigned int u32;

__device__ unsigned g_cnt[L_];                       // 0..510 step barriers, 511 pre-barrier
__device__ __nv_bfloat16 g_hh[2][B_ * H_];           // h hi, ping-pong
__device__ __nv_bfloat16 g_hl[2][B_ * H_];           // h lo, ping-pong

// ---------------- small helpers ----------------
__device__ __forceinline__ void unpack2(float& lo, float& hi, ull v) {
    unsigned a, b;
    asm("mov.b64 {%0, %1}, %2;" : "=r"(a), "=r"(b) : "l"(v));
    lo = __uint_as_float(a); hi = __uint_as_float(b);
}
__device__ __forceinline__ ull add2(ull a, ull b) {
    ull d;
    asm("add.rn.f32x2 %0, %1, %2;" : "=l"(d) : "l"(a), "l"(b));
    return d;
}
__device__ __forceinline__ void cp_async16g(char* smem_dst, const void* gsrc) {
    unsigned s = (unsigned)__cvta_generic_to_shared(smem_dst);
    asm volatile("cp.async.cg.shared.global [%0], [%1], 16;\n" :: "r"(s), "l"(gsrc));
}
__device__ __forceinline__ void cp_commit() { asm volatile("cp.async.commit_group;\n"); }
template <int N>
__device__ __forceinline__ void cp_wait() { asm volatile("cp.async.wait_group %0;\n" :: "n"(N)); }

__device__ __forceinline__ void ldsm_x4(u32& r0, u32& r1, u32& r2, u32& r3, u32 addr) {
    asm volatile("ldmatrix.sync.aligned.m8n8.x4.shared.b16 {%0,%1,%2,%3}, [%4];"
                 : "=r"(r0), "=r"(r1), "=r"(r2), "=r"(r3) : "r"(addr));
}
__device__ __forceinline__ void mma_bf16(float* c, u32 a0, u32 a1, u32 a2, u32 a3,
                                         u32 b0, u32 b1) {
    asm volatile("mma.sync.aligned.m16n8k16.row.col.f32.bf16.bf16.f32 "
                 "{%0,%1,%2,%3}, {%4,%5,%6,%7}, {%8,%9}, {%0,%1,%2,%3};"
                 : "+f"(c[0]), "+f"(c[1]), "+f"(c[2]), "+f"(c[3])
                 : "r"(a0), "r"(a1), "r"(a2), "r"(a3), "r"(b0), "r"(b1));
}
__device__ __forceinline__ void split_bf16(float v, __nv_bfloat16& h, __nv_bfloat16& l) {
    h = __float2bfloat16(v);
    l = __float2bfloat16(v - __bfloat162float(h));
}
__device__ __forceinline__ void split4(float4 v, uint2& hi, uint2& lo) {
    __nv_bfloat16 h0,h1,h2,h3,l0,l1,l2,l3;
    split_bf16(v.x,h0,l0); split_bf16(v.y,h1,l1);
    split_bf16(v.z,h2,l2); split_bf16(v.w,h3,l3);
    __nv_bfloat162 ph0 = {h0,h1}, ph1 = {h2,h3}, pl0 = {l0,l1}, pl1 = {l2,l3};
    hi.x = *reinterpret_cast<u32*>(&ph0); hi.y = *reinterpret_cast<u32*>(&ph1);
    lo.x = *reinterpret_cast<u32*>(&pl0); lo.y = *reinterpret_cast<u32*>(&pl1);
}

// ============================================================================
// Phase 1: bf16-split tensor-core GEMM, 2-stage SMEM pipeline
// ============================================================================
#define P1_BM 128
#define P1_BN 128
#define P1_BK 32
#define LDS_  40
#define P1_PL   (P1_BM * LDS_)        // elems per plane (5120)
#define P1_PLB  (P1_PL * 2)           // bytes per plane (10240)
#define P1_SMEM (2 * 4 * P1_PLB)      // 81920 bytes (2 stages x 4 planes)

__global__ void __launch_bounds__(256)
gemm_bf16split(const float* __restrict__ A, const float* __restrict__ B,
               const float* __restrict__ bias, float* __restrict__ C,
               int M, int N, int K)
{
    extern __shared__ __align__(16) __nv_bfloat16 s1[];   // [2][4][P1_PL]

    const int tid  = threadIdx.x;
    const int warp = tid >> 5;
    const int lane = tid & 31;
    const int wm   = warp & 3;
    const int wn   = warp >> 2;
    const int bm   = blockIdx.y * P1_BM;
    const int bn   = blockIdx.x * P1_BN;

    const float* agp[4];
    const float* bgp[4];
    int arow[4], ac4[4];
#pragma unroll
    for (int i = 0; i < 4; ++i) {
        int f = tid + i * 256;
        arow[i] = f >> 3; ac4[i] = f & 7;
        agp[i] = A + (size_t)(bm + arow[i]) * K + ac4[i] * 4;
        bgp[i] = B + (size_t)(bn + arow[i]) * K + ac4[i] * 4;
    }

    const u32 lrow = lane & 15;
    const u32 lkof = (lane >> 4) * 16;
    const u32 aoff0 = (wm * 32 + lrow) * (LDS_ * 2) + lkof;   // within-plane byte offset
    const u32 boff0 = (wn * 64 + lrow) * (LDS_ * 2) + lkof;
    const u32 sbase = (u32)__cvta_generic_to_shared(s1);

    float acc[2][8][4];
#pragma unroll
    for (int mt = 0; mt < 2; ++mt)
#pragma unroll
        for (int nt = 0; nt < 8; ++nt)
#pragma unroll
            for (int q = 0; q < 4; ++q) acc[mt][nt][q] = 0.f;

    // prefetch tile 0 and stage to buffer 0
    float4 pa[4], pb[4];
#pragma unroll
    for (int i = 0; i < 4; ++i) {
        pa[i] = *reinterpret_cast<const float4*>(agp[i]);
        pb[i] = *reinterpret_cast<const float4*>(bgp[i]);
    }
#pragma unroll
    for (int i = 0; i < 4; ++i) {
        uint2 hi, lo;
        int e = arow[i] * LDS_ + ac4[i] * 4;
        split4(pa[i], hi, lo);
        *reinterpret_cast<uint2*>(&s1[0 * 4 * P1_PL + 0 * P1_PL + e]) = hi;
        *reinterpret_cast<uint2*>(&s1[0 * 4 * P1_PL + 1 * P1_PL + e]) = lo;
        split4(pb[i], hi, lo);
        *reinterpret_cast<uint2*>(&s1[0 * 4 * P1_PL + 2 * P1_PL + e]) = hi;
        *reinterpret_cast<uint2*>(&s1[0 * 4 * P1_PL + 3 * P1_PL + e]) = lo;
    }
    __syncthreads();

    const int NKT = K / P1_BK;          // 32
    for (int kt = 0; kt < NKT; ++kt) {
        const int cur = kt & 1;
        const int nxt = cur ^ 1;
        const u32 cb  = sbase + cur * 4 * P1_PLB;

        // issue LDG for next tile first (hides under MMA)
        if (kt + 1 < NKT) {
#pragma unroll
            for (int i = 0; i < 4; ++i) {
                pa[i] = *reinterpret_cast<const float4*>(agp[i] + (kt + 1) * P1_BK);
                pb[i] = *reinterpret_cast<const float4*>(bgp[i] + (kt + 1) * P1_BK);
            }
        }

        // MMA on current buffer
#pragma unroll
        for (int ks = 0; ks < 2; ++ks) {
            const u32 kb = ks * 32;
            u32 ah[2][4], al[2][4];
#pragma unroll
            for (int mt = 0; mt < 2; ++mt) {
                u32 off = aoff0 + mt * 16 * (LDS_ * 2) + kb;
                ldsm_x4(ah[mt][0], ah[mt][1], ah[mt][2], ah[mt][3], cb + 0 * P1_PLB + off);
                ldsm_x4(al[mt][0], al[mt][1], al[mt][2], al[mt][3], cb + 1 * P1_PLB + off);
            }
#pragma unroll
            for (int np = 0; np < 4; ++np) {
                u32 off = boff0 + np * 16 * (LDS_ * 2) + kb;
                u32 bh0, bh1, bh2, bh3, bl0, bl1, bl2, bl3;
                ldsm_x4(bh0, bh1, bh2, bh3, cb + 2 * P1_PLB + off);
                ldsm_x4(bl0, bl1, bl2, bl3, cb + 3 * P1_PLB + off);
#pragma unroll
                for (int mt = 0; mt < 2; ++mt) {
                    mma_bf16(acc[mt][2*np],   ah[mt][0],ah[mt][1],ah[mt][2],ah[mt][3], bh0, bh2);
                    mma_bf16(acc[mt][2*np],   ah[mt][0],ah[mt][1],ah[mt][2],ah[mt][3], bl0, bl2);
                    mma_bf16(acc[mt][2*np],   al[mt][0],al[mt][1],al[mt][2],al[mt][3], bh0, bh2);
                    mma_bf16(acc[mt][2*np+1], ah[mt][0],ah[mt][1],ah[mt][2],ah[mt][3], bh1, bh3);
                    mma_bf16(acc[mt][2*np+1], ah[mt][0],ah[mt][1],ah[mt][2],ah[mt][3], bl1, bl3);
                    mma_bf16(acc[mt][2*np+1], al[mt][0],al[mt][1],al[mt][2],al[mt][3], bh1, bh3);
                }
            }
        }

        // stage next tile into the other buffer (overlaps MMA issue above)
        if (kt + 1 < NKT) {
#pragma unroll
            for (int i = 0; i < 4; ++i) {
                uint2 hi, lo;
                int e = arow[i] * LDS_ + ac4[i] * 4;
                split4(pa[i], hi, lo);
                *reinterpret_cast<uint2*>(&s1[nxt * 4 * P1_PL + 0 * P1_PL + e]) = hi;
                *reinterpret_cast<uint2*>(&s1[nxt * 4 * P1_PL + 1 * P1_PL + e]) = lo;
                split4(pb[i], hi, lo);
                *reinterpret_cast<uint2*>(&s1[nxt * 4 * P1_PL + 2 * P1_PL + e]) = hi;
                *reinterpret_cast<uint2*>(&s1[nxt * 4 * P1_PL + 3 * P1_PL + e]) = lo;
            }
        }
        __syncthreads();
    }

    const int qrow = lane >> 2;
    const int qcol = (lane & 3) * 2;
#pragma unroll
    for (int mt = 0; mt < 2; ++mt) {
        const int r0 = bm + wm * 32 + mt * 16 + qrow;
#pragma unroll
        for (int nt = 0; nt < 8; ++nt) {
            const int c = bn + wn * 64 + nt * 8 + qcol;
            float2 bs = *reinterpret_cast<const float2*>(bias + c);
            float2 v0; v0.x = acc[mt][nt][0] + bs.x; v0.y = acc[mt][nt][1] + bs.y;
            float2 v1; v1.x = acc[mt][nt][2] + bs.x; v1.y = acc[mt][nt][3] + bs.y;
            *reinterpret_cast<float2*>(C + (size_t)r0 * N + c)       = v0;
            *reinterpret_cast<float2*>(C + (size_t)(r0 + 8) * N + c) = v1;
        }
    }
}

// ============================================================================
// Phase 2: tensor-core persistent recurrence (R7-proven barrier + xi prefetch)
// ============================================================================
#define WH_STRIDE   1032
#define WH_PLANE    (32 * WH_STRIDE * 2)
#define CH_STRIDE   136
#define CH_PLANE    (32 * CH_STRIDE * 2)
#define SLOT_BYTES  (2 * CH_PLANE)
#define RING_OFF    (2 * WH_PLANE)
#define SMEM2_BYTES (RING_OFF + 4 * SLOT_BYTES)

__device__ __forceinline__ void issue_hchunk(const __nv_bfloat16* __restrict__ srcH,
                                             const __nv_bfloat16* __restrict__ srcL,
                                             int rb, int ch, char* slot, int tid) {
#pragma unroll
    for (int s = 0; s < 2; ++s) {
        int f     = tid + s * BLK2;
        int plane = f >> 9;
        int idx   = f & 511;
        int row   = idx >> 4;
        int seg   = idx & 15;
        const __nv_bfloat16* src = (plane ? srcL : srcH)
                                   + (size_t)(rb + row) * H_ + ch * 128 + seg * 8;
        cp_async16g(slot + plane * CH_PLANE + row * (CH_STRIDE * 2) + seg * 16, src);
    }
}

__global__ void __launch_bounds__(BLK2, 1)
rnn_steps_tc(const float* __restrict__ h0, const float* __restrict__ Wh,
             const float* __restrict__ bh, float* __restrict__ out)
{
    extern __shared__ __align__(16) char smem2[];
    __nv_bfloat16* whh = reinterpret_cast<__nv_bfloat16*>(smem2);
    __nv_bfloat16* whl = whh + 32 * WH_STRIDE;
    char* ring = smem2 + RING_OFF;

    const int tid  = threadIdx.x;
    const int warp = tid >> 5;
    const int lane = tid & 31;
    const int cgrp = blockIdx.x & 31;
    const int bgrp = blockIdx.x >> 5;
    const int n0   = cgrp * 32;
    const int rb   = bgrp * 32;

    // ---- convert this CTA's Wh slice to bf16 hi/lo in SMEM ----
    for (int idx = tid; idx < 32 * 256; idx += BLK2) {
        int c  = idx >> 8;
        int kv = idx & 255;
        float4 v = *reinterpret_cast<const float4*>(Wh + (size_t)(n0 + c) * H_ + kv * 4);
        uint2 hi, lo;
        split4(v, hi, lo);
        *reinterpret_cast<uint2*>(whh + c * WH_STRIDE + kv * 4) = hi;
        *reinterpret_cast<uint2*>(whl + c * WH_STRIDE + kv * 4) = lo;
    }

    // ---- convert h0 -> g_hh[0]/g_hl[0] (each CTA a disjoint 1024-elem piece) ----
    {
        int base = blockIdx.x * 1024 + tid * 2;
        float2 v = *reinterpret_cast<const float2*>(h0 + base);
        __nv_bfloat16 ha, la, hb, lb;
        split_bf16(v.x, ha, la);
        split_bf16(v.y, hb, lb);
        __nv_bfloat162 ph = {ha, hb}, pl = {la, lb};
        reinterpret_cast<u32*>(g_hh[0])[base >> 1] = *reinterpret_cast<u32*>(&ph);
        reinterpret_cast<u32*>(g_hl[0])[base >> 1] = *reinterpret_cast<u32*>(&pl);
    }
    __threadfence();
    __syncthreads();
    if (tid == 0) {
        atomicAdd(&g_cnt[511], 1u);
        while (((volatile unsigned*)g_cnt)[511] < NCTA) { __nanosleep(64); }
        __threadfence();
    }
    __syncthreads();

    // ---- per-thread constants ----
    const u32 lrow  = lane & 15;
    const u32 lkof  = (lane >> 4) * 16;
    const int myk16 = warp & 7;
    const int chpar = warp >> 3;
    const u32 whh_b = (u32)__cvta_generic_to_shared(whh);
    const u32 whl_b = (u32)__cvta_generic_to_shared(whl);

    const int e     = tid;
    const int lrow2 = e >> 4;
    const int lcol2 = (e & 15) * 2;
    const int grow  = rb + lrow2;
    const int gcol  = n0 + lcol2;
    const float2 wb = *reinterpret_cast<const float2*>(bh + gcol);
    const size_t o_off = (size_t)grow * H_ + gcol;

    float* pbuf = reinterpret_cast<float*>(ring);
    const int prow  = lane >> 2;
    const int pcol2 = (lane & 3) * 2;

    for (int t = 0; t < L_; ++t) {
        const __nv_bfloat16* srcH = g_hh[t & 1];
        const __nv_bfloat16* srcL = g_hl[t & 1];
        float* ot = out + (size_t)t * B_ * H_;

        // prefetch xi for this step's epilogue (independent of h)
        const float2 xi = *reinterpret_cast<const float2*>(ot + o_off);

#pragma unroll
        for (int ch = 0; ch < 4; ++ch) {
            issue_hchunk(srcH, srcL, rb, ch, ring + (ch & 3) * SLOT_BYTES, tid);
            cp_commit();
        }

        float acc[2][4][4];
#pragma unroll
        for (int mt = 0; mt < 2; ++mt)
#pragma unroll
            for (int nt = 0; nt < 4; ++nt)
#pragma unroll
                for (int q = 0; q < 4; ++q) acc[mt][nt][q] = 0.f;

#pragma unroll
        for (int r = 0; r < 4; ++r) {
            if (r < 3) cp_wait<2>(); else cp_wait<0>();
            __syncthreads();

            const int ch = 2 * r + chpar;
            const u32 slot_hi = (u32)__cvta_generic_to_shared(ring + (ch & 3) * SLOT_BYTES);
            const u32 slot_lo = slot_hi + CH_PLANE;
            const int kglob   = ch * 128 + myk16 * 16;

            u32 ah[2][4], al[2][4];
#pragma unroll
            for (int mt = 0; mt < 2; ++mt) {
                u32 off = (mt * 16 + lrow) * (CH_STRIDE * 2) + myk16 * 32 + lkof;
                ldsm_x4(ah[mt][0], ah[mt][1], ah[mt][2], ah[mt][3], slot_hi + off);
                ldsm_x4(al[mt][0], al[mt][1], al[mt][2], al[mt][3], slot_lo + off);
            }
#pragma unroll
            for (int np = 0; np < 2; ++np) {
                u32 boff = (np * 16 + lrow) * (WH_STRIDE * 2) + kglob * 2 + lkof;
                u32 bh0, bh1, bh2, bh3, bl0, bl1, bl2, bl3;
                ldsm_x4(bh0, bh1, bh2, bh3, whh_b + boff);
                ldsm_x4(bl0, bl1, bl2, bl3, whl_b + boff);
#pragma unroll
                for (int mt = 0; mt < 2; ++mt) {
                    mma_bf16(acc[mt][2*np],   ah[mt][0],ah[mt][1],ah[mt][2],ah[mt][3], bh0, bh2);
                    mma_bf16(acc[mt][2*np],   ah[mt][0],ah[mt][1],ah[mt][2],ah[mt][3], bl0, bl2);
                    mma_bf16(acc[mt][2*np],   al[mt][0],al[mt][1],al[mt][2],al[mt][3], bh0, bh2);
                    mma_bf16(acc[mt][2*np+1], ah[mt][0],ah[mt][1],ah[mt][2],ah[mt][3], bh1, bh3);
                    mma_bf16(acc[mt][2*np+1], ah[mt][0],ah[mt][1],ah[mt][2],ah[mt][3], bl1, bl3);
                    mma_bf16(acc[mt][2*np+1], al[mt][0],al[mt][1],al[mt][2],al[mt][3], bh1, bh3);
                }
            }
            __syncthreads();
            if (r < 2) {
                issue_hchunk(srcH, srcL, rb, 2*r + 4, ring + ((2*r)     & 3) * SLOT_BYTES, tid);
                cp_commit();
                issue_hchunk(srcH, srcL, rb, 2*r + 5, ring + ((2*r + 1) & 3) * SLOT_BYTES, tid);
                cp_commit();
            }
        }

        // ---- store partials (ring smem reused as [16][1024] fp32) ----
#pragma unroll
        for (int mt = 0; mt < 2; ++mt)
#pragma unroll
            for (int nt = 0; nt < 4; ++nt) {
                int b = warp * 1024 + (mt * 16 + prow) * 32 + nt * 8 + pcol2;
                float2 v0 = {acc[mt][nt][0], acc[mt][nt][1]};
                float2 v1 = {acc[mt][nt][2], acc[mt][nt][3]};
                *reinterpret_cast<float2*>(&pbuf[b])          = v0;
                *reinterpret_cast<float2*>(&pbuf[b + 8 * 32]) = v1;
            }
        __syncthreads();

        // ---- 16-way k-reduction + fused epilogue ----
        ull s2 = *reinterpret_cast<const ull*>(&pbuf[2 * e]);
#pragma unroll
        for (int w = 1; w < 16; ++w)
            s2 = add2(s2, *reinterpret_cast<const ull*>(&pbuf[w * 1024 + 2 * e]));
        float s0, s1;
        unpack2(s0, s1, s2);

        float v0 = tanhf(s0 + wb.x + xi.x);
        float v1 = tanhf(s1 + wb.y + xi.y);
        float2 vv = {v0, v1};
        *reinterpret_cast<float2*>(ot + o_off) = vv;

        __nv_bfloat16 ha, la, hb2, lb2;
        split_bf16(v0, ha, la);
        split_bf16(v1, hb2, lb2);
        __nv_bfloat162 ph = {ha, hb2}, pl = {la, lb2};
        const int nxt = (t + 1) & 1;
        reinterpret_cast<u32*>(g_hh[nxt])[o_off >> 1] = *reinterpret_cast<u32*>(&ph);
        reinterpret_cast<u32*>(g_hl[nxt])[o_off >> 1] = *reinterpret_cast<u32*>(&pl);

        // single 128-CTA global barrier (R7-proven)
        if (t < L_ - 1) {
            __threadfence();
            __syncthreads();
            if (tid == 0) {
                atomicAdd(&g_cnt[t], 1u);
                while (((volatile unsigned*)g_cnt)[t] < NCTA) { __nanosleep(64); }
                __threadfence();
            }
            __syncthreads();
        }
    }
}

__global__ void reset_cnt() {
    int i = blockIdx.x * blockDim.x + threadIdx.x;
    if (i < L_) g_cnt[i] = 0;
}

// ---------------- launcher ----------------
extern "C" void kernel_launch(void* const* d_in, const int* in_sizes, int n_in,
                              void* d_out, int out_size)
{
    const float* x    = (const float*)d_in[0];  // [L,B,D]
    const float* h0   = (const float*)d_in[1];  // [B,H]
    const float* Wi_w = (const float*)d_in[2];  // [H,D]
    const float* Wi_b = (const float*)d_in[3];  // [H]
    const float* Wh_w = (const float*)d_in[4];  // [H,H]
    const float* Wh_b = (const float*)d_in[5];  // [H]
    float* out = (float*)d_out;                 // [L,B,H]

    // Phase 1: out = x @ Wi^T + bi  (tensor cores, bf16 split, 2-stage pipe)
    {
        const int M1 = L_ * B_;
        cudaFuncSetAttribute(gemm_bf16split, cudaFuncAttributeMaxDynamicSharedMemorySize,
                             P1_SMEM);
        dim3 grid(H_ / P1_BN, M1 / P1_BM);
        gemm_bf16split<<<grid, 256, P1_SMEM>>>(x, Wi_w, Wi_b, out, M1, H_, H_);
    }

    // Phase 2: persistent tensor-core recurrence
    {
        cudaFuncSetAttribute(rnn_steps_tc, cudaFuncAttributeMaxDynamicSharedMemorySize,
                             SMEM2_BYTES);
        rnn_steps_tc<<<NCTA, BLK2, SMEM2_BYTES>>>(h0, Wh_w, Wh_b, out);
    }

    // Phase 3: reset barrier counters for the next graph replay
    reset_cnt<<<(L_ + 255) / 256, 256>>>();
}

// round 12
// speedup vs baseline: 1.1864x; 1.1864x over previous
#include <cuda_runtime.h>
#include <cuda_bf16.h>
#include <math.h>

// ============================================================================
// RNN: h_t = tanh(x_t @ Wi^T + bi + h_{t-1} @ Wh^T + bh)
// Phase 1: bf16 hi/lo split tensor-core GEMM (R7-exact, proven 1.67ms).
// Phase 2: persistent tensor-core recurrence. h carried between steps in
//          MMA-FRAGMENT ORDER in global memory: consumers load A operands
//          directly into registers with 4 coalesced LDG.128 per warp per
//          round (no smem staging, no cp.async, no mbarrier, no intra-step
//          syncthreads). Wh resident in smem (ldsm). 16-warp k-split,
//          mma.m16n8k16 x3 passes, smem k-reduce, fused xi+tanh epilogue,
//          single 128-CTA atomic global barrier per step (proven).
// Shapes hardcoded: L=512, B=128, D=H=1024 (fp32).
// ============================================================================

#define L_    512
#define B_    128
#define H_    1024
#define NCTA  128
#define BLK2  512

typedef unsigned long long ull;
typedef unsigned int u32;

__device__ unsigned g_cnt[L_];   // 0..510 step barriers, 511 pre-barrier

// h carry in MMA-fragment order:
//   g_ha[pingpong][bgrp][plane(0=hi,1=lo)][16384 u32]
//   u32 slot for fragment (ch, q, mt), lane, j:  ((ch*8+q)*2+mt)*128 + lane*4 + j
//   (ch = k-chunk 0..7, q = k16 0..7, mt = row-half 0..1, j = a0..a3)
__device__ __align__(128) u32 g_ha[2][4][2][16384];

// ---------------- small helpers ----------------
__device__ __forceinline__ void unpack2(float& lo, float& hi, ull v) {
    unsigned a, b;
    asm("mov.b64 {%0, %1}, %2;" : "=r"(a), "=r"(b) : "l"(v));
    lo = __uint_as_float(a); hi = __uint_as_float(b);
}
__device__ __forceinline__ ull add2(ull a, ull b) {
    ull d;
    asm("add.rn.f32x2 %0, %1, %2;" : "=l"(d) : "l"(a), "l"(b));
    return d;
}
__device__ __forceinline__ void ldsm_x4(u32& r0, u32& r1, u32& r2, u32& r3, u32 addr) {
    asm volatile("ldmatrix.sync.aligned.m8n8.x4.shared.b16 {%0,%1,%2,%3}, [%4];"
                 : "=r"(r0), "=r"(r1), "=r"(r2), "=r"(r3) : "r"(addr));
}
__device__ __forceinline__ void mma_bf16(float* c, u32 a0, u32 a1, u32 a2, u32 a3,
                                         u32 b0, u32 b1) {
    asm volatile("mma.sync.aligned.m16n8k16.row.col.f32.bf16.bf16.f32 "
                 "{%0,%1,%2,%3}, {%4,%5,%6,%7}, {%8,%9}, {%0,%1,%2,%3};"
                 : "+f"(c[0]), "+f"(c[1]), "+f"(c[2]), "+f"(c[3])
                 : "r"(a0), "r"(a1), "r"(a2), "r"(a3), "r"(b0), "r"(b1));
}
__device__ __forceinline__ void split_bf16(float v, __nv_bfloat16& h, __nv_bfloat16& l) {
    h = __float2bfloat16(v);
    l = __float2bfloat16(v - __bfloat162float(h));
}
__device__ __forceinline__ void split4(float4 v, uint2& hi, uint2& lo) {
    __nv_bfloat16 h0,h1,h2,h3,l0,l1,l2,l3;
    split_bf16(v.x,h0,l0); split_bf16(v.y,h1,l1);
    split_bf16(v.z,h2,l2); split_bf16(v.w,h3,l3);
    __nv_bfloat162 ph0 = {h0,h1}, ph1 = {h2,h3}, pl0 = {l0,l1}, pl1 = {l2,l3};
    hi.x = *reinterpret_cast<u32*>(&ph0); hi.y = *reinterpret_cast<u32*>(&ph1);
    lo.x = *reinterpret_cast<u32*>(&pl0); lo.y = *reinterpret_cast<u32*>(&pl1);
}

// ============================================================================
// Phase 1: bf16-split tensor-core GEMM (R7-exact, static smem)
// ============================================================================
#define P1_BM 128
#define P1_BN 128
#define P1_BK 32
#define LDS_  40

__global__ void __launch_bounds__(256)
gemm_bf16split(const float* __restrict__ A, const float* __restrict__ B,
               const float* __restrict__ bias, float* __restrict__ C,
               int M, int N, int K)
{
    __shared__ __align__(16) __nv_bfloat16 sAh[P1_BM * LDS_];
    __shared__ __align__(16) __nv_bfloat16 sAl[P1_BM * LDS_];
    __shared__ __align__(16) __nv_bfloat16 sBh[P1_BN * LDS_];
    __shared__ __align__(16) __nv_bfloat16 sBl[P1_BN * LDS_];

    const int tid  = threadIdx.x;
    const int warp = tid >> 5;
    const int lane = tid & 31;
    const int wm   = warp & 3;
    const int wn   = warp >> 2;
    const int bm   = blockIdx.y * P1_BM;
    const int bn   = blockIdx.x * P1_BN;

    const float* agp[4];
    const float* bgp[4];
    int arow[4], ac4[4];
#pragma unroll
    for (int i = 0; i < 4; ++i) {
        int f = tid + i * 256;
        arow[i] = f >> 3; ac4[i] = f & 7;
        agp[i] = A + (size_t)(bm + arow[i]) * K + ac4[i] * 4;
        bgp[i] = B + (size_t)(bn + arow[i]) * K + ac4[i] * 4;
    }

    const u32 lrow = lane & 15;
    const u32 lkof = (lane >> 4) * 16;
    const u32 aoff0 = (wm * 32 + lrow) * (LDS_ * 2) + lkof;
    const u32 boff0 = (wn * 64 + lrow) * (LDS_ * 2) + lkof;
    const u32 sAh_b = (u32)__cvta_generic_to_shared(sAh);
    const u32 sAl_b = (u32)__cvta_generic_to_shared(sAl);
    const u32 sBh_b = (u32)__cvta_generic_to_shared(sBh);
    const u32 sBl_b = (u32)__cvta_generic_to_shared(sBl);

    float acc[2][8][4];
#pragma unroll
    for (int mt = 0; mt < 2; ++mt)
#pragma unroll
        for (int nt = 0; nt < 8; ++nt)
#pragma unroll
            for (int q = 0; q < 4; ++q) acc[mt][nt][q] = 0.f;

    float4 pa[4], pb[4];
#pragma unroll
    for (int i = 0; i < 4; ++i) {
        pa[i] = *reinterpret_cast<const float4*>(agp[i]);
        pb[i] = *reinterpret_cast<const float4*>(bgp[i]);
    }

    const int NKT = K / P1_BK;
    for (int kt = 0; kt < NKT; ++kt) {
#pragma unroll
        for (int i = 0; i < 4; ++i) {
            uint2 hi, lo;
            int e = arow[i] * LDS_ + ac4[i] * 4;
            split4(pa[i], hi, lo);
            *reinterpret_cast<uint2*>(&sAh[e]) = hi;
            *reinterpret_cast<uint2*>(&sAl[e]) = lo;
            split4(pb[i], hi, lo);
            *reinterpret_cast<uint2*>(&sBh[e]) = hi;
            *reinterpret_cast<uint2*>(&sBl[e]) = lo;
        }
        __syncthreads();

        if (kt + 1 < NKT) {
#pragma unroll
            for (int i = 0; i < 4; ++i) {
                pa[i] = *reinterpret_cast<const float4*>(agp[i] + (kt + 1) * P1_BK);
                pb[i] = *reinterpret_cast<const float4*>(bgp[i] + (kt + 1) * P1_BK);
            }
        }

#pragma unroll
        for (int ks = 0; ks < 2; ++ks) {
            const u32 kb = ks * 32;
            u32 ah[2][4], al[2][4];
#pragma unroll
            for (int mt = 0; mt < 2; ++mt) {
                u32 off = aoff0 + mt * 16 * (LDS_ * 2) + kb;
                ldsm_x4(ah[mt][0], ah[mt][1], ah[mt][2], ah[mt][3], sAh_b + off);
                ldsm_x4(al[mt][0], al[mt][1], al[mt][2], al[mt][3], sAl_b + off);
            }
#pragma unroll
            for (int np = 0; np < 4; ++np) {
                u32 off = boff0 + np * 16 * (LDS_ * 2) + kb;
                u32 bh0, bh1, bh2, bh3, bl0, bl1, bl2, bl3;
                ldsm_x4(bh0, bh1, bh2, bh3, sBh_b + off);
                ldsm_x4(bl0, bl1, bl2, bl3, sBl_b + off);
#pragma unroll
                for (int mt = 0; mt < 2; ++mt) {
                    mma_bf16(acc[mt][2*np],   ah[mt][0],ah[mt][1],ah[mt][2],ah[mt][3], bh0, bh2);
                    mma_bf16(acc[mt][2*np],   ah[mt][0],ah[mt][1],ah[mt][2],ah[mt][3], bl0, bl2);
                    mma_bf16(acc[mt][2*np],   al[mt][0],al[mt][1],al[mt][2],al[mt][3], bh0, bh2);
                    mma_bf16(acc[mt][2*np+1], ah[mt][0],ah[mt][1],ah[mt][2],ah[mt][3], bh1, bh3);
                    mma_bf16(acc[mt][2*np+1], ah[mt][0],ah[mt][1],ah[mt][2],ah[mt][3], bl1, bl3);
                    mma_bf16(acc[mt][2*np+1], al[mt][0],al[mt][1],al[mt][2],al[mt][3], bh1, bh3);
                }
            }
        }
        __syncthreads();
    }

    const int qrow = lane >> 2;
    const int qcol = (lane & 3) * 2;
#pragma unroll
    for (int mt = 0; mt < 2; ++mt) {
        const int r0 = bm + wm * 32 + mt * 16 + qrow;
#pragma unroll
        for (int nt = 0; nt < 8; ++nt) {
            const int c = bn + wn * 64 + nt * 8 + qcol;
            float2 bs = *reinterpret_cast<const float2*>(bias + c);
            float2 v0; v0.x = acc[mt][nt][0] + bs.x; v0.y = acc[mt][nt][1] + bs.y;
            float2 v1; v1.x = acc[mt][nt][2] + bs.x; v1.y = acc[mt][nt][3] + bs.y;
            *reinterpret_cast<float2*>(C + (size_t)r0 * N + c)       = v0;
            *reinterpret_cast<float2*>(C + (size_t)(r0 + 8) * N + c) = v1;
        }
    }
}

// ============================================================================
// Phase 2: persistent recurrence, A operands LDG'd from fragment-ordered h
// SMEM: Wh hi/lo [32][1032] bf16 (129KB) + pbuf [16][1024] fp32 (64KB)
// ============================================================================
#define WH_STRIDE   1032
#define WH_PLANE    (32 * WH_STRIDE * 2)          // 66048 B
#define PBUF_OFF    (2 * WH_PLANE)                 // 132096
#define SMEM2_BYTES (PBUF_OFF + 16 * 1024 * 4)     // 197632

__global__ void __launch_bounds__(BLK2, 1)
rnn_steps_tc(const float* __restrict__ h0, const float* __restrict__ Wh,
             const float* __restrict__ bh, float* __restrict__ out)
{
    extern __shared__ __align__(16) char smem2[];
    __nv_bfloat16* whh = reinterpret_cast<__nv_bfloat16*>(smem2);
    __nv_bfloat16* whl = whh + 32 * WH_STRIDE;
    float* pbuf = reinterpret_cast<float*>(smem2 + PBUF_OFF);

    const int tid  = threadIdx.x;
    const int warp = tid >> 5;
    const int lane = tid & 31;
    const int cgrp = blockIdx.x & 31;
    const int bgrp = blockIdx.x >> 5;
    const int n0   = cgrp * 32;

    // ---- convert this CTA's Wh slice to bf16 hi/lo in SMEM ----
    for (int idx = tid; idx < 32 * 256; idx += BLK2) {
        int c  = idx >> 8;
        int kv = idx & 255;
        float4 v = *reinterpret_cast<const float4*>(Wh + (size_t)(n0 + c) * H_ + kv * 4);
        uint2 hi, lo;
        split4(v, hi, lo);
        *reinterpret_cast<uint2*>(whh + c * WH_STRIDE + kv * 4) = hi;
        *reinterpret_cast<uint2*>(whl + c * WH_STRIDE + kv * 4) = lo;
    }

    // ---- convert h0 into fragment-ordered g_ha[0] (disjoint pieces) ----
    {
        int g    = blockIdx.x * 1024 + tid * 2;       // even element index
        int row  = g >> 10;
        int col  = g & 1023;                          // even
        float2 v = *reinterpret_cast<const float2*>(h0 + g);
        __nv_bfloat16 ha, la, hb, lb;
        split_bf16(v.x, ha, la);
        split_bf16(v.y, hb, lb);
        __nv_bfloat162 ph = {ha, hb}, pl = {la, lb};
        int bg = row >> 5, lr = row & 31;
        int ch = col >> 7, c0 = col & 127, q = c0 >> 4, kk = c0 & 15;
        int mt = lr >> 4, rl = lr & 15;
        int j    = (kk >> 3) * 2 + (rl >> 3);
        int lnp  = (rl & 7) * 4 + ((kk & 7) >> 1);
        int slot = ((ch * 8 + q) * 2 + mt) * 128 + lnp * 4 + j;
        g_ha[0][bg][0][slot] = *reinterpret_cast<u32*>(&ph);
        g_ha[0][bg][1][slot] = *reinterpret_cast<u32*>(&pl);
    }
    __threadfence();
    __syncthreads();
    if (tid == 0) {
        atomicAdd(&g_cnt[511], 1u);
        while (((volatile unsigned*)g_cnt)[511] < NCTA) { __nanosleep(64); }
        __threadfence();
    }
    __syncthreads();

    // ---- per-thread constants ----
    const int myk16 = warp & 7;                 // k16 index within a chunk
    const int chpar = warp >> 3;                // chunk parity handled by this warp
    const u32 whh_b = (u32)__cvta_generic_to_shared(whh);
    const u32 whl_b = (u32)__cvta_generic_to_shared(whl);
    const u32 lrow  = lane & 15;
    const u32 lkof  = (lane >> 4) * 16;

    // A-fragment u32 index for (ch, q=myk16, mt): ((ch*8+q)*2+mt)*128 + lane*4
    const int afrag0 = (chpar * 8 + myk16) * 2 * 128 + lane * 4;   // ch = chpar
    const int astep  = 2 * 8 * 2 * 128;                             // +2 chunks

    // reduction / epilogue mapping: thread e owns local elems (2e, 2e+1)
    const int e     = tid;
    const int lrow2 = e >> 4;
    const int lcol2 = (e & 15) * 2;
    const int grow  = bgrp * 32 + lrow2;
    const int gcol  = n0 + lcol2;
    const float2 wb = *reinterpret_cast<const float2*>(bh + gcol);
    const size_t o_off = (size_t)grow * H_ + gcol;

    // epilogue fragment slot for this thread's h pair (constant)
    int ep_slot;
    {
        int ch = gcol >> 7, c0 = gcol & 127, q = c0 >> 4, kk = c0 & 15;
        int mt = lrow2 >> 4, rl = lrow2 & 15;
        int j   = (kk >> 3) * 2 + (rl >> 3);
        int lnp = (rl & 7) * 4 + ((kk & 7) >> 1);
        ep_slot = ((ch * 8 + q) * 2 + mt) * 128 + lnp * 4 + j;
    }

    const int prow  = lane >> 2;
    const int pcol2 = (lane & 3) * 2;

    for (int t = 0; t < L_; ++t) {
        const u32* pAh = g_ha[t & 1][bgrp][0];
        const u32* pAl = g_ha[t & 1][bgrp][1];
        float* ot = out + (size_t)t * B_ * H_;
        const float2 xi = *reinterpret_cast<const float2*>(ot + o_off);

        float acc[2][4][4];
#pragma unroll
        for (int mt = 0; mt < 2; ++mt)
#pragma unroll
            for (int nt = 0; nt < 4; ++nt)
#pragma unroll
                for (int q = 0; q < 4; ++q) acc[mt][nt][q] = 0.f;

        // prefetch round 0 A fragments (registers, no smem)
        uint4 cAh0 = *reinterpret_cast<const uint4*>(pAh + afrag0);
        uint4 cAh1 = *reinterpret_cast<const uint4*>(pAh + afrag0 + 128);
        uint4 cAl0 = *reinterpret_cast<const uint4*>(pAl + afrag0);
        uint4 cAl1 = *reinterpret_cast<const uint4*>(pAl + afrag0 + 128);

#pragma unroll
        for (int r = 0; r < 4; ++r) {
            // prefetch next round
            uint4 nAh0, nAh1, nAl0, nAl1;
            if (r < 3) {
                const int na = afrag0 + (r + 1) * astep;
                nAh0 = *reinterpret_cast<const uint4*>(pAh + na);
                nAh1 = *reinterpret_cast<const uint4*>(pAh + na + 128);
                nAl0 = *reinterpret_cast<const uint4*>(pAl + na);
                nAl1 = *reinterpret_cast<const uint4*>(pAl + na + 128);
            }

            const int ch    = 2 * r + chpar;
            const int kglob = ch * 128 + myk16 * 16;
            const u32 ah[2][4] = {{cAh0.x, cAh0.y, cAh0.z, cAh0.w},
                                  {cAh1.x, cAh1.y, cAh1.z, cAh1.w}};
            const u32 al[2][4] = {{cAl0.x, cAl0.y, cAl0.z, cAl0.w},
                                  {cAl1.x, cAl1.y, cAl1.z, cAl1.w}};
#pragma unroll
            for (int np = 0; np < 2; ++np) {
                u32 boff = (np * 16 + lrow) * (WH_STRIDE * 2) + kglob * 2 + lkof;
                u32 bh0, bh1, bh2, bh3, bl0, bl1, bl2, bl3;
                ldsm_x4(bh0, bh1, bh2, bh3, whh_b + boff);
                ldsm_x4(bl0, bl1, bl2, bl3, whl_b + boff);
#pragma unroll
                for (int mt = 0; mt < 2; ++mt) {
                    mma_bf16(acc[mt][2*np],   ah[mt][0],ah[mt][1],ah[mt][2],ah[mt][3], bh0, bh2);
                    mma_bf16(acc[mt][2*np],   ah[mt][0],ah[mt][1],ah[mt][2],ah[mt][3], bl0, bl2);
                    mma_bf16(acc[mt][2*np],   al[mt][0],al[mt][1],al[mt][2],al[mt][3], bh0, bh2);
                    mma_bf16(acc[mt][2*np+1], ah[mt][0],ah[mt][1],ah[mt][2],ah[mt][3], bh1, bh3);
                    mma_bf16(acc[mt][2*np+1], ah[mt][0],ah[mt][1],ah[mt][2],ah[mt][3], bl1, bl3);
                    mma_bf16(acc[mt][2*np+1], al[mt][0],al[mt][1],al[mt][2],al[mt][3], bh1, bh3);
                }
            }
            if (r < 3) { cAh0 = nAh0; cAh1 = nAh1; cAl0 = nAl0; cAl1 = nAl1; }
        }

        // ---- store partials ----
#pragma unroll
        for (int mt = 0; mt < 2; ++mt)
#pragma unroll
            for (int nt = 0; nt < 4; ++nt) {
                int b = warp * 1024 + (mt * 16 + prow) * 32 + nt * 8 + pcol2;
                float2 v0 = {acc[mt][nt][0], acc[mt][nt][1]};
                float2 v1 = {acc[mt][nt][2], acc[mt][nt][3]};
                *reinterpret_cast<float2*>(&pbuf[b])          = v0;
                *reinterpret_cast<float2*>(&pbuf[b + 8 * 32]) = v1;
            }
        __syncthreads();

        // ---- 16-way k-reduction + fused epilogue ----
        ull s2 = *reinterpret_cast<const ull*>(&pbuf[2 * e]);
#pragma unroll
        for (int w = 1; w < 16; ++w)
            s2 = add2(s2, *reinterpret_cast<const ull*>(&pbuf[w * 1024 + 2 * e]));
        float s0, s1;
        unpack2(s0, s1, s2);

        float v0 = tanhf(s0 + wb.x + xi.x);
        float v1 = tanhf(s1 + wb.y + xi.y);
        float2 vv = {v0, v1};
        *reinterpret_cast<float2*>(ot + o_off) = vv;

        // write h_t pair into fragment-ordered carry for step t+1
        __nv_bfloat16 ha, la, hb2, lb2;
        split_bf16(v0, ha, la);
        split_bf16(v1, hb2, lb2);
        __nv_bfloat162 ph = {ha, hb2}, pl = {la, lb2};
        const int nxt = (t + 1) & 1;
        g_ha[nxt][bgrp][0][ep_slot] = *reinterpret_cast<u32*>(&ph);
        g_ha[nxt][bgrp][1][ep_slot] = *reinterpret_cast<u32*>(&pl);

        // single 128-CTA global barrier (proven)
        if (t < L_ - 1) {
            __threadfence();
            __syncthreads();
            if (tid == 0) {
                atomicAdd(&g_cnt[t], 1u);
                while (((volatile unsigned*)g_cnt)[t] < NCTA) { __nanosleep(64); }
                __threadfence();
            }
            __syncthreads();
        }
    }
}

__global__ void reset_cnt() {
    int i = blockIdx.x * blockDim.x + threadIdx.x;
    if (i < L_) g_cnt[i] = 0;
}

// ---------------- launcher ----------------
extern "C" void kernel_launch(void* const* d_in, const int* in_sizes, int n_in,
                              void* d_out, int out_size)
{
    const float* x    = (const float*)d_in[0];  // [L,B,D]
    const float* h0   = (const float*)d_in[1];  // [B,H]
    const float* Wi_w = (const float*)d_in[2];  // [H,D]
    const float* Wi_b = (const float*)d_in[3];  // [H]
    const float* Wh_w = (const float*)d_in[4];  // [H,H]
    const float* Wh_b = (const float*)d_in[5];  // [H]
    float* out = (float*)d_out;                 // [L,B,H]

    // Phase 1: out = x @ Wi^T + bi  (tensor cores, bf16 split)
    {
        const int M1 = L_ * B_;
        dim3 grid(H_ / P1_BN, M1 / P1_BM);
        gemm_bf16split<<<grid, 256>>>(x, Wi_w, Wi_b, out, M1, H_, H_);
    }

    // Phase 2: persistent tensor-core recurrence
    {
        cudaFuncSetAttribute(rnn_steps_tc, cudaFuncAttributeMaxDynamicSharedMemorySize,
                             SMEM2_BYTES);
        rnn_steps_tc<<<NCTA, BLK2, SMEM2_BYTES>>>(h0, Wh_w, Wh_b, out);
    }

    // Phase 3: reset barrier counters for the next graph replay
    reset_cnt<<<(L_ + 255) / 256, 256>>>();
}

// round 13
// speedup vs baseline: 1.2342x; 1.0403x over previous
#include <cuda_runtime.h>
#include <cuda_bf16.h>
#include <math.h>

// ============================================================================
// RNN: h_t = tanh(x_t @ Wi^T + bi + h_{t-1} @ Wh^T + bh)
// Phase 1: bf16 hi/lo split tensor-core GEMM, retiled 128x64 so 2 CTAs
//          co-reside per SM (reg-capped via __launch_bounds__(256,2)) --
//          cross-CTA overlap fills the sync/staging bubbles.
// Phase 2: persistent tensor-core recurrence (R12-proven): h carried in
//          MMA-fragment order in global, A operands LDG'd straight to
//          registers, Wh resident in smem, single atomic global barrier.
//          + next-step xi prefetched before the barrier (hidden under spin).
// Shapes hardcoded: L=512, B=128, D=H=1024 (fp32).
// ============================================================================

#define L_    512
#define B_    128
#define H_    1024
#define NCTA  128
#define BLK2  512

typedef unsigned long long ull;
typedef unsigned int u32;

__device__ unsigned g_cnt[L_];   // 0..510 step barriers, 511 pre-barrier

// h carry in MMA-fragment order:
//   g_ha[pingpong][bgrp][plane(0=hi,1=lo)][16384 u32]
//   u32 slot for fragment (ch, q, mt), lane, j:  ((ch*8+q)*2+mt)*128 + lane*4 + j
__device__ __align__(128) u32 g_ha[2][4][2][16384];

// ---------------- small helpers ----------------
__device__ __forceinline__ void unpack2(float& lo, float& hi, ull v) {
    unsigned a, b;
    asm("mov.b64 {%0, %1}, %2;" : "=r"(a), "=r"(b) : "l"(v));
    lo = __uint_as_float(a); hi = __uint_as_float(b);
}
__device__ __forceinline__ ull add2(ull a, ull b) {
    ull d;
    asm("add.rn.f32x2 %0, %1, %2;" : "=l"(d) : "l"(a), "l"(b));
    return d;
}
__device__ __forceinline__ void ldsm_x4(u32& r0, u32& r1, u32& r2, u32& r3, u32 addr) {
    asm volatile("ldmatrix.sync.aligned.m8n8.x4.shared.b16 {%0,%1,%2,%3}, [%4];"
                 : "=r"(r0), "=r"(r1), "=r"(r2), "=r"(r3) : "r"(addr));
}
__device__ __forceinline__ void mma_bf16(float* c, u32 a0, u32 a1, u32 a2, u32 a3,
                                         u32 b0, u32 b1) {
    asm volatile("mma.sync.aligned.m16n8k16.row.col.f32.bf16.bf16.f32 "
                 "{%0,%1,%2,%3}, {%4,%5,%6,%7}, {%8,%9}, {%0,%1,%2,%3};"
                 : "+f"(c[0]), "+f"(c[1]), "+f"(c[2]), "+f"(c[3])
                 : "r"(a0), "r"(a1), "r"(a2), "r"(a3), "r"(b0), "r"(b1));
}
__device__ __forceinline__ void split_bf16(float v, __nv_bfloat16& h, __nv_bfloat16& l) {
    h = __float2bfloat16(v);
    l = __float2bfloat16(v - __bfloat162float(h));
}
__device__ __forceinline__ void split4(float4 v, uint2& hi, uint2& lo) {
    __nv_bfloat16 h0,h1,h2,h3,l0,l1,l2,l3;
    split_bf16(v.x,h0,l0); split_bf16(v.y,h1,l1);
    split_bf16(v.z,h2,l2); split_bf16(v.w,h3,l3);
    __nv_bfloat162 ph0 = {h0,h1}, ph1 = {h2,h3}, pl0 = {l0,l1}, pl1 = {l2,l3};
    hi.x = *reinterpret_cast<u32*>(&ph0); hi.y = *reinterpret_cast<u32*>(&ph1);
    lo.x = *reinterpret_cast<u32*>(&pl0); lo.y = *reinterpret_cast<u32*>(&pl1);
}

// ============================================================================
// Phase 1: bf16-split tensor-core GEMM, 128x64 tile, 2 CTAs/SM
// ============================================================================
#define P1_BM 128
#define P1_BN 64
#define P1_BK 32
#define LDS_  40

__global__ void __launch_bounds__(256, 2)
gemm_bf16split(const float* __restrict__ A, const float* __restrict__ B,
               const float* __restrict__ bias, float* __restrict__ C,
               int M, int N, int K)
{
    __shared__ __align__(16) __nv_bfloat16 sAh[P1_BM * LDS_];
    __shared__ __align__(16) __nv_bfloat16 sAl[P1_BM * LDS_];
    __shared__ __align__(16) __nv_bfloat16 sBh[P1_BN * LDS_];
    __shared__ __align__(16) __nv_bfloat16 sBl[P1_BN * LDS_];

    const int tid  = threadIdx.x;
    const int warp = tid >> 5;
    const int lane = tid & 31;
    const int wm   = warp & 3;          // 4 warp-rows of 32
    const int wn   = warp >> 2;         // 2 warp-cols of 32
    const int bm   = blockIdx.y * P1_BM;
    const int bn   = blockIdx.x * P1_BN;

    // A: 128x32 floats = 1024 float4 -> 4/thread.  B: 64x32 = 512 -> 2/thread.
    const float* agp[4];
    int arow[4], ac4[4];
#pragma unroll
    for (int i = 0; i < 4; ++i) {
        int f = tid + i * 256;
        arow[i] = f >> 3; ac4[i] = f & 7;
        agp[i] = A + (size_t)(bm + arow[i]) * K + ac4[i] * 4;
    }
    const float* bgp[2];
    int brow[2], bc4[2];
#pragma unroll
    for (int i = 0; i < 2; ++i) {
        int f = tid + i * 256;
        brow[i] = f >> 3; bc4[i] = f & 7;
        bgp[i] = B + (size_t)(bn + brow[i]) * K + bc4[i] * 4;
    }

    const u32 lrow = lane & 15;
    const u32 lkof = (lane >> 4) * 16;
    const u32 aoff0 = (wm * 32 + lrow) * (LDS_ * 2) + lkof;
    const u32 boff0 = (wn * 32 + lrow) * (LDS_ * 2) + lkof;
    const u32 sAh_b = (u32)__cvta_generic_to_shared(sAh);
    const u32 sAl_b = (u32)__cvta_generic_to_shared(sAl);
    const u32 sBh_b = (u32)__cvta_generic_to_shared(sBh);
    const u32 sBl_b = (u32)__cvta_generic_to_shared(sBl);

    float acc[2][4][4];
#pragma unroll
    for (int mt = 0; mt < 2; ++mt)
#pragma unroll
        for (int nt = 0; nt < 4; ++nt)
#pragma unroll
            for (int q = 0; q < 4; ++q) acc[mt][nt][q] = 0.f;

    float4 pa[4], pb[2];
#pragma unroll
    for (int i = 0; i < 4; ++i) pa[i] = *reinterpret_cast<const float4*>(agp[i]);
#pragma unroll
    for (int i = 0; i < 2; ++i) pb[i] = *reinterpret_cast<const float4*>(bgp[i]);

    const int NKT = K / P1_BK;
    for (int kt = 0; kt < NKT; ++kt) {
#pragma unroll
        for (int i = 0; i < 4; ++i) {
            uint2 hi, lo;
            int e = arow[i] * LDS_ + ac4[i] * 4;
            split4(pa[i], hi, lo);
            *reinterpret_cast<uint2*>(&sAh[e]) = hi;
            *reinterpret_cast<uint2*>(&sAl[e]) = lo;
        }
#pragma unroll
        for (int i = 0; i < 2; ++i) {
            uint2 hi, lo;
            int e = brow[i] * LDS_ + bc4[i] * 4;
            split4(pb[i], hi, lo);
            *reinterpret_cast<uint2*>(&sBh[e]) = hi;
            *reinterpret_cast<uint2*>(&sBl[e]) = lo;
        }
        __syncthreads();

        if (kt + 1 < NKT) {
#pragma unroll
            for (int i = 0; i < 4; ++i)
                pa[i] = *reinterpret_cast<const float4*>(agp[i] + (kt + 1) * P1_BK);
#pragma unroll
            for (int i = 0; i < 2; ++i)
                pb[i] = *reinterpret_cast<const float4*>(bgp[i] + (kt + 1) * P1_BK);
        }

#pragma unroll
        for (int ks = 0; ks < 2; ++ks) {
            const u32 kb = ks * 32;
            u32 ah[2][4], al[2][4];
#pragma unroll
            for (int mt = 0; mt < 2; ++mt) {
                u32 off = aoff0 + mt * 16 * (LDS_ * 2) + kb;
                ldsm_x4(ah[mt][0], ah[mt][1], ah[mt][2], ah[mt][3], sAh_b + off);
                ldsm_x4(al[mt][0], al[mt][1], al[mt][2], al[mt][3], sAl_b + off);
            }
#pragma unroll
            for (int np = 0; np < 2; ++np) {
                u32 off = boff0 + np * 16 * (LDS_ * 2) + kb;
                u32 bh0, bh1, bh2, bh3, bl0, bl1, bl2, bl3;
                ldsm_x4(bh0, bh1, bh2, bh3, sBh_b + off);
                ldsm_x4(bl0, bl1, bl2, bl3, sBl_b + off);
#pragma unroll
                for (int mt = 0; mt < 2; ++mt) {
                    mma_bf16(acc[mt][2*np],   ah[mt][0],ah[mt][1],ah[mt][2],ah[mt][3], bh0, bh2);
                    mma_bf16(acc[mt][2*np],   ah[mt][0],ah[mt][1],ah[mt][2],ah[mt][3], bl0, bl2);
                    mma_bf16(acc[mt][2*np],   al[mt][0],al[mt][1],al[mt][2],al[mt][3], bh0, bh2);
                    mma_bf16(acc[mt][2*np+1], ah[mt][0],ah[mt][1],ah[mt][2],ah[mt][3], bh1, bh3);
                    mma_bf16(acc[mt][2*np+1], ah[mt][0],ah[mt][1],ah[mt][2],ah[mt][3], bl1, bl3);
                    mma_bf16(acc[mt][2*np+1], al[mt][0],al[mt][1],al[mt][2],al[mt][3], bh1, bh3);
                }
            }
        }
        __syncthreads();
    }

    const int qrow = lane >> 2;
    const int qcol = (lane & 3) * 2;
#pragma unroll
    for (int mt = 0; mt < 2; ++mt) {
        const int r0 = bm + wm * 32 + mt * 16 + qrow;
#pragma unroll
        for (int nt = 0; nt < 4; ++nt) {
            const int c = bn + wn * 32 + nt * 8 + qcol;
            float2 bs = *reinterpret_cast<const float2*>(bias + c);
            float2 v0; v0.x = acc[mt][nt][0] + bs.x; v0.y = acc[mt][nt][1] + bs.y;
            float2 v1; v1.x = acc[mt][nt][2] + bs.x; v1.y = acc[mt][nt][3] + bs.y;
            *reinterpret_cast<float2*>(C + (size_t)r0 * N + c)       = v0;
            *reinterpret_cast<float2*>(C + (size_t)(r0 + 8) * N + c) = v1;
        }
    }
}

// ============================================================================
// Phase 2: persistent recurrence, A operands LDG'd from fragment-ordered h
// (R12-proven; only change: next-step xi prefetched before the barrier)
// ============================================================================
#define WH_STRIDE   1032
#define WH_PLANE    (32 * WH_STRIDE * 2)          // 66048 B
#define PBUF_OFF    (2 * WH_PLANE)                 // 132096
#define SMEM2_BYTES (PBUF_OFF + 16 * 1024 * 4)     // 197632

__global__ void __launch_bounds__(BLK2, 1)
rnn_steps_tc(const float* __restrict__ h0, const float* __restrict__ Wh,
             const float* __restrict__ bh, float* __restrict__ out)
{
    extern __shared__ __align__(16) char smem2[];
    __nv_bfloat16* whh = reinterpret_cast<__nv_bfloat16*>(smem2);
    __nv_bfloat16* whl = whh + 32 * WH_STRIDE;
    float* pbuf = reinterpret_cast<float*>(smem2 + PBUF_OFF);

    const int tid  = threadIdx.x;
    const int warp = tid >> 5;
    const int lane = tid & 31;
    const int cgrp = blockIdx.x & 31;
    const int bgrp = blockIdx.x >> 5;
    const int n0   = cgrp * 32;

    // ---- convert this CTA's Wh slice to bf16 hi/lo in SMEM ----
    for (int idx = tid; idx < 32 * 256; idx += BLK2) {
        int c  = idx >> 8;
        int kv = idx & 255;
        float4 v = *reinterpret_cast<const float4*>(Wh + (size_t)(n0 + c) * H_ + kv * 4);
        uint2 hi, lo;
        split4(v, hi, lo);
        *reinterpret_cast<uint2*>(whh + c * WH_STRIDE + kv * 4) = hi;
        *reinterpret_cast<uint2*>(whl + c * WH_STRIDE + kv * 4) = lo;
    }

    // ---- convert h0 into fragment-ordered g_ha[0] (disjoint pieces) ----
    {
        int g    = blockIdx.x * 1024 + tid * 2;       // even element index
        int row  = g >> 10;
        int col  = g & 1023;                          // even
        float2 v = *reinterpret_cast<const float2*>(h0 + g);
        __nv_bfloat16 ha, la, hb, lb;
        split_bf16(v.x, ha, la);
        split_bf16(v.y, hb, lb);
        __nv_bfloat162 ph = {ha, hb}, pl = {la, lb};
        int bg = row >> 5, lr = row & 31;
        int ch = col >> 7, c0 = col & 127, q = c0 >> 4, kk = c0 & 15;
        int mt = lr >> 4, rl = lr & 15;
        int j    = (kk >> 3) * 2 + (rl >> 3);
        int lnp  = (rl & 7) * 4 + ((kk & 7) >> 1);
        int slot = ((ch * 8 + q) * 2 + mt) * 128 + lnp * 4 + j;
        g_ha[0][bg][0][slot] = *reinterpret_cast<u32*>(&ph);
        g_ha[0][bg][1][slot] = *reinterpret_cast<u32*>(&pl);
    }
    __threadfence();
    __syncthreads();
    if (tid == 0) {
        atomicAdd(&g_cnt[511], 1u);
        while (((volatile unsigned*)g_cnt)[511] < NCTA) { __nanosleep(64); }
        __threadfence();
    }
    __syncthreads();

    // ---- per-thread constants ----
    const int myk16 = warp & 7;
    const int chpar = warp >> 3;
    const u32 whh_b = (u32)__cvta_generic_to_shared(whh);
    const u32 whl_b = (u32)__cvta_generic_to_shared(whl);
    const u32 lrow  = lane & 15;
    const u32 lkof  = (lane >> 4) * 16;

    const int afrag0 = (chpar * 8 + myk16) * 2 * 128 + lane * 4;
    const int astep  = 2 * 8 * 2 * 128;

    const int e     = tid;
    const int lrow2 = e >> 4;
    const int lcol2 = (e & 15) * 2;
    const int grow  = bgrp * 32 + lrow2;
    const int gcol  = n0 + lcol2;
    const float2 wb = *reinterpret_cast<const float2*>(bh + gcol);
    const size_t o_off = (size_t)grow * H_ + gcol;

    int ep_slot;
    {
        int ch = gcol >> 7, c0 = gcol & 127, q = c0 >> 4, kk = c0 & 15;
        int mt = lrow2 >> 4, rl = lrow2 & 15;
        int j   = (kk >> 3) * 2 + (rl >> 3);
        int lnp = (rl & 7) * 4 + ((kk & 7) >> 1);
        ep_slot = ((ch * 8 + q) * 2 + mt) * 128 + lnp * 4 + j;
    }

    const int prow  = lane >> 2;
    const int pcol2 = (lane & 3) * 2;

    // xi for step 0 (rows of `out` hold phase-1 xi until overwritten at their step)
    float2 xi = *reinterpret_cast<const float2*>(out + o_off);

    for (int t = 0; t < L_; ++t) {
        const u32* pAh = g_ha[t & 1][bgrp][0];
        const u32* pAl = g_ha[t & 1][bgrp][1];
        float* ot = out + (size_t)t * B_ * H_;

        float acc[2][4][4];
#pragma unroll
        for (int mt = 0; mt < 2; ++mt)
#pragma unroll
            for (int nt = 0; nt < 4; ++nt)
#pragma unroll
                for (int q = 0; q < 4; ++q) acc[mt][nt][q] = 0.f;

        // prefetch round 0 A fragments (registers, no smem)
        uint4 cAh0 = *reinterpret_cast<const uint4*>(pAh + afrag0);
        uint4 cAh1 = *reinterpret_cast<const uint4*>(pAh + afrag0 + 128);
        uint4 cAl0 = *reinterpret_cast<const uint4*>(pAl + afrag0);
        uint4 cAl1 = *reinterpret_cast<const uint4*>(pAl + afrag0 + 128);

#pragma unroll
        for (int r = 0; r < 4; ++r) {
            uint4 nAh0, nAh1, nAl0, nAl1;
            if (r < 3) {
                const int na = afrag0 + (r + 1) * astep;
                nAh0 = *reinterpret_cast<const uint4*>(pAh + na);
                nAh1 = *reinterpret_cast<const uint4*>(pAh + na + 128);
                nAl0 = *reinterpret_cast<const uint4*>(pAl + na);
                nAl1 = *reinterpret_cast<const uint4*>(pAl + na + 128);
            }

            const int ch    = 2 * r + chpar;
            const int kglob = ch * 128 + myk16 * 16;
            const u32 ah[2][4] = {{cAh0.x, cAh0.y, cAh0.z, cAh0.w},
                                  {cAh1.x, cAh1.y, cAh1.z, cAh1.w}};
            const u32 al[2][4] = {{cAl0.x, cAl0.y, cAl0.z, cAl0.w},
                                  {cAl1.x, cAl1.y, cAl1.z, cAl1.w}};
#pragma unroll
            for (int np = 0; np < 2; ++np) {
                u32 boff = (np * 16 + lrow) * (WH_STRIDE * 2) + kglob * 2 + lkof;
                u32 bh0, bh1, bh2, bh3, bl0, bl1, bl2, bl3;
                ldsm_x4(bh0, bh1, bh2, bh3, whh_b + boff);
                ldsm_x4(bl0, bl1, bl2, bl3, whl_b + boff);
#pragma unroll
                for (int mt = 0; mt < 2; ++mt) {
                    mma_bf16(acc[mt][2*np],   ah[mt][0],ah[mt][1],ah[mt][2],ah[mt][3], bh0, bh2);
                    mma_bf16(acc[mt][2*np],   ah[mt][0],ah[mt][1],ah[mt][2],ah[mt][3], bl0, bl2);
                    mma_bf16(acc[mt][2*np],   al[mt][0],al[mt][1],al[mt][2],al[mt][3], bh0, bh2);
                    mma_bf16(acc[mt][2*np+1], ah[mt][0],ah[mt][1],ah[mt][2],ah[mt][3], bh1, bh3);
                    mma_bf16(acc[mt][2*np+1], ah[mt][0],ah[mt][1],ah[mt][2],ah[mt][3], bl1, bl3);
                    mma_bf16(acc[mt][2*np+1], al[mt][0],al[mt][1],al[mt][2],al[mt][3], bh1, bh3);
                }
            }
            if (r < 3) { cAh0 = nAh0; cAh1 = nAh1; cAl0 = nAl0; cAl1 = nAl1; }
        }

        // ---- store partials ----
#pragma unroll
        for (int mt = 0; mt < 2; ++mt)
#pragma unroll
            for (int nt = 0; nt < 4; ++nt) {
                int b = warp * 1024 + (mt * 16 + prow) * 32 + nt * 8 + pcol2;
                float2 v0 = {acc[mt][nt][0], acc[mt][nt][1]};
                float2 v1 = {acc[mt][nt][2], acc[mt][nt][3]};
                *reinterpret_cast<float2*>(&pbuf[b])          = v0;
                *reinterpret_cast<float2*>(&pbuf[b + 8 * 32]) = v1;
            }
        __syncthreads();

        // ---- 16-way k-reduction + fused epilogue ----
        ull s2 = *reinterpret_cast<const ull*>(&pbuf[2 * e]);
#pragma unroll
        for (int w = 1; w < 16; ++w)
            s2 = add2(s2, *reinterpret_cast<const ull*>(&pbuf[w * 1024 + 2 * e]));
        float s0, s1;
        unpack2(s0, s1, s2);

        float v0 = tanhf(s0 + wb.x + xi.x);
        float v1 = tanhf(s1 + wb.y + xi.y);
        float2 vv = {v0, v1};
        *reinterpret_cast<float2*>(ot + o_off) = vv;

        // write h_t pair into fragment-ordered carry for step t+1
        __nv_bfloat16 ha, la, hb2, lb2;
        split_bf16(v0, ha, la);
        split_bf16(v1, hb2, lb2);
        __nv_bfloat162 ph = {ha, hb2}, pl = {la, lb2};
        const int nxt = (t + 1) & 1;
        g_ha[nxt][bgrp][0][ep_slot] = *reinterpret_cast<u32*>(&ph);
        g_ha[nxt][bgrp][1][ep_slot] = *reinterpret_cast<u32*>(&pl);

        if (t < L_ - 1) {
            // prefetch next step's xi (phase-1 data; untouched until step t+1) --
            // issued before the barrier so the LDG completes under the spin
            xi = *reinterpret_cast<const float2*>(ot + B_ * H_ + o_off);

            __threadfence();
            __syncthreads();
            if (tid == 0) {
                atomicAdd(&g_cnt[t], 1u);
                while (((volatile unsigned*)g_cnt)[t] < NCTA) { __nanosleep(64); }
                __threadfence();
            }
            __syncthreads();
        }
    }
}

__global__ void reset_cnt() {
    int i = blockIdx.x * blockDim.x + threadIdx.x;
    if (i < L_) g_cnt[i] = 0;
}

// ---------------- launcher ----------------
extern "C" void kernel_launch(void* const* d_in, const int* in_sizes, int n_in,
                              void* d_out, int out_size)
{
    const float* x    = (const float*)d_in[0];  // [L,B,D]
    const float* h0   = (const float*)d_in[1];  // [B,H]
    const float* Wi_w = (const float*)d_in[2];  // [H,D]
    const float* Wi_b = (const float*)d_in[3];  // [H]
    const float* Wh_w = (const float*)d_in[4];  // [H,H]
    const float* Wh_b = (const float*)d_in[5];  // [H]
    float* out = (float*)d_out;                 // [L,B,H]

    // Phase 1: out = x @ Wi^T + bi  (tensor cores, bf16 split, 2 CTAs/SM)
    {
        const int M1 = L_ * B_;
        dim3 grid(H_ / P1_BN, M1 / P1_BM);
        gemm_bf16split<<<grid, 256>>>(x, Wi_w, Wi_b, out, M1, H_, H_);
    }

    // Phase 2: persistent tensor-core recurrence
    {
        cudaFuncSetAttribute(rnn_steps_tc, cudaFuncAttributeMaxDynamicSharedMemorySize,
                             SMEM2_BYTES);
        rnn_steps_tc<<<NCTA, BLK2, SMEM2_BYTES>>>(h0, Wh_w, Wh_b, out);
    }

    // Phase 3: reset barrier counters for the next graph replay
    reset_cnt<<<(L_ + 255) / 256, 256>>>();
}

// round 15
// speedup vs baseline: 1.2411x; 1.0056x over previous
#include <cuda_runtime.h>
#include <cuda_bf16.h>
#include <math.h>

// ============================================================================
// RNN: h_t = tanh(x_t @ Wi^T + bi + h_{t-1} @ Wh^T + bh)
// Phase 1: bf16 hi/lo split mma.sync GEMM (R13 tile: 128x64, 2 CTAs/SM) with
//          FAST TRUNCATION SPLIT: hi = top 16 bits (PRMT), lo = rn(v - hi).
//          Cuts conversion ALU ~2x vs round-based split.
// Phase 2: persistent tensor-core recurrence (R13-proven): h carried in
//          MMA-fragment order in global, A LDG'd to registers, Wh resident
//          in smem, single atomic global barrier + xi prefetch. Fast split
//          in the epilogue; nanosleep(32) spin.
// NOTE: tcgen05 unusable here (harness targets compute_100 virtual arch).
// Shapes hardcoded: L=512, B=128, D=H=1024 (fp32).
// ============================================================================

#define L_    512
#define B_    128
#define H_    1024
#define NCTA  128
#define BLK2  512

typedef unsigned long long ull;
typedef unsigned int u32;

__device__ unsigned g_cnt[L_];   // 0..510 step barriers, 511 pre-barrier

// h carry in MMA-fragment order:
//   g_ha[pingpong][bgrp][plane(0=hi,1=lo)][16384 u32]
__device__ __align__(128) u32 g_ha[2][4][2][16384];

// ---------------- small helpers ----------------
__device__ __forceinline__ void unpack2(float& lo, float& hi, ull v) {
    unsigned a, b;
    asm("mov.b64 {%0, %1}, %2;" : "=r"(a), "=r"(b) : "l"(v));
    lo = __uint_as_float(a); hi = __uint_as_float(b);
}
__device__ __forceinline__ ull add2(ull a, ull b) {
    ull d;
    asm("add.rn.f32x2 %0, %1, %2;" : "=l"(d) : "l"(a), "l"(b));
    return d;
}
__device__ __forceinline__ void ldsm_x4(u32& r0, u32& r1, u32& r2, u32& r3, u32 addr) {
    asm volatile("ldmatrix.sync.aligned.m8n8.x4.shared.b16 {%0,%1,%2,%3}, [%4];"
                 : "=r"(r0), "=r"(r1), "=r"(r2), "=r"(r3) : "r"(addr));
}
__device__ __forceinline__ void mma_bf16(float* c, u32 a0, u32 a1, u32 a2, u32 a3,
                                         u32 b0, u32 b1) {
    asm volatile("mma.sync.aligned.m16n8k16.row.col.f32.bf16.bf16.f32 "
                 "{%0,%1,%2,%3}, {%4,%5,%6,%7}, {%8,%9}, {%0,%1,%2,%3};"
                 : "+f"(c[0]), "+f"(c[1]), "+f"(c[2]), "+f"(c[3])
                 : "r"(a0), "r"(a1), "r"(a2), "r"(a3), "r"(b0), "r"(b1));
}
// legacy round-based split (used only in one-time setup paths)
__device__ __forceinline__ void split_bf16(float v, __nv_bfloat16& h, __nv_bfloat16& l) {
    h = __float2bfloat16(v);
    l = __float2bfloat16(v - __bfloat162float(h));
}
// FAST truncation split: hi = top16(v) (exact trunc), lo = rn_bf16(v - hi).
// Packs two hi's with one PRMT; two lo's with one packed cvt.
__device__ __forceinline__ u32 cvt2bf16(float hi_lane, float lo_lane) {
    u32 r;
    asm("cvt.rn.bf16x2.f32 %0, %1, %2;" : "=r"(r) : "f"(hi_lane), "f"(lo_lane));
    return r;
}
__device__ __forceinline__ void split4_fast(float4 v, uint2& hi, uint2& lo) {
    u32 x0 = __float_as_uint(v.x), x1 = __float_as_uint(v.y);
    u32 x2 = __float_as_uint(v.z), x3 = __float_as_uint(v.w);
    hi.x = __byte_perm(x0, x1, 0x7632);                 // [bf16(x0), bf16(x1)] (trunc)
    hi.y = __byte_perm(x2, x3, 0x7632);
    float l0 = v.x - __uint_as_float(x0 & 0xFFFF0000u);
    float l1 = v.y - __uint_as_float(x1 & 0xFFFF0000u);
    float l2 = v.z - __uint_as_float(x2 & 0xFFFF0000u);
    float l3 = v.w - __uint_as_float(x3 & 0xFFFF0000u);
    lo.x = cvt2bf16(l1, l0);
    lo.y = cvt2bf16(l3, l2);
}
__device__ __forceinline__ void split2_fast(float v0, float v1, u32& hi, u32& lo) {
    u32 b0 = __float_as_uint(v0), b1 = __float_as_uint(v1);
    hi = __byte_perm(b0, b1, 0x7632);
    float l0 = v0 - __uint_as_float(b0 & 0xFFFF0000u);
    float l1 = v1 - __uint_as_float(b1 & 0xFFFF0000u);
    lo = cvt2bf16(l1, l0);
}

// ============================================================================
// Phase 1: bf16-split tensor-core GEMM, 128x64 tile, 2 CTAs/SM (R13 config)
// ============================================================================
#define P1_BM 128
#define P1_BN 64
#define P1_BK 32
#define LDS_  40

__global__ void __launch_bounds__(256, 2)
gemm_bf16split(const float* __restrict__ A, const float* __restrict__ B,
               const float* __restrict__ bias, float* __restrict__ C,
               int M, int N, int K)
{
    __shared__ __align__(16) __nv_bfloat16 sAh[P1_BM * LDS_];
    __shared__ __align__(16) __nv_bfloat16 sAl[P1_BM * LDS_];
    __shared__ __align__(16) __nv_bfloat16 sBh[P1_BN * LDS_];
    __shared__ __align__(16) __nv_bfloat16 sBl[P1_BN * LDS_];

    const int tid  = threadIdx.x;
    const int warp = tid >> 5;
    const int lane = tid & 31;
    const int wm   = warp & 3;
    const int wn   = warp >> 2;
    const int bm   = blockIdx.y * P1_BM;
    const int bn   = blockIdx.x * P1_BN;

    const float* agp[4];
    int arow[4], ac4[4];
#pragma unroll
    for (int i = 0; i < 4; ++i) {
        int f = tid + i * 256;
        arow[i] = f >> 3; ac4[i] = f & 7;
        agp[i] = A + (size_t)(bm + arow[i]) * K + ac4[i] * 4;
    }
    const float* bgp[2];
    int brow[2], bc4[2];
#pragma unroll
    for (int i = 0; i < 2; ++i) {
        int f = tid + i * 256;
        brow[i] = f >> 3; bc4[i] = f & 7;
        bgp[i] = B + (size_t)(bn + brow[i]) * K + bc4[i] * 4;
    }

    const u32 lrow = lane & 15;
    const u32 lkof = (lane >> 4) * 16;
    const u32 aoff0 = (wm * 32 + lrow) * (LDS_ * 2) + lkof;
    const u32 boff0 = (wn * 32 + lrow) * (LDS_ * 2) + lkof;
    const u32 sAh_b = (u32)__cvta_generic_to_shared(sAh);
    const u32 sAl_b = (u32)__cvta_generic_to_shared(sAl);
    const u32 sBh_b = (u32)__cvta_generic_to_shared(sBh);
    const u32 sBl_b = (u32)__cvta_generic_to_shared(sBl);

    float acc[2][4][4];
#pragma unroll
    for (int mt = 0; mt < 2; ++mt)
#pragma unroll
        for (int nt = 0; nt < 4; ++nt)
#pragma unroll
            for (int q = 0; q < 4; ++q) acc[mt][nt][q] = 0.f;

    float4 pa[4], pb[2];
#pragma unroll
    for (int i = 0; i < 4; ++i) pa[i] = *reinterpret_cast<const float4*>(agp[i]);
#pragma unroll
    for (int i = 0; i < 2; ++i) pb[i] = *reinterpret_cast<const float4*>(bgp[i]);

    const int NKT = K / P1_BK;
    for (int kt = 0; kt < NKT; ++kt) {
#pragma unroll
        for (int i = 0; i < 4; ++i) {
            uint2 hi, lo;
            int e = arow[i] * LDS_ + ac4[i] * 4;
            split4_fast(pa[i], hi, lo);
            *reinterpret_cast<uint2*>(&sAh[e]) = hi;
            *reinterpret_cast<uint2*>(&sAl[e]) = lo;
        }
#pragma unroll
        for (int i = 0; i < 2; ++i) {
            uint2 hi, lo;
            int e = brow[i] * LDS_ + bc4[i] * 4;
            split4_fast(pb[i], hi, lo);
            *reinterpret_cast<uint2*>(&sBh[e]) = hi;
            *reinterpret_cast<uint2*>(&sBl[e]) = lo;
        }
        __syncthreads();

        if (kt + 1 < NKT) {
#pragma unroll
            for (int i = 0; i < 4; ++i)
                pa[i] = *reinterpret_cast<const float4*>(agp[i] + (kt + 1) * P1_BK);
#pragma unroll
            for (int i = 0; i < 2; ++i)
                pb[i] = *reinterpret_cast<const float4*>(bgp[i] + (kt + 1) * P1_BK);
        }

#pragma unroll
        for (int ks = 0; ks < 2; ++ks) {
            const u32 kb = ks * 32;
            u32 ah[2][4], al[2][4];
#pragma unroll
            for (int mt = 0; mt < 2; ++mt) {
                u32 off = aoff0 + mt * 16 * (LDS_ * 2) + kb;
                ldsm_x4(ah[mt][0], ah[mt][1], ah[mt][2], ah[mt][3], sAh_b + off);
                ldsm_x4(al[mt][0], al[mt][1], al[mt][2], al[mt][3], sAl_b + off);
            }
#pragma unroll
            for (int np = 0; np < 2; ++np) {
                u32 off = boff0 + np * 16 * (LDS_ * 2) + kb;
                u32 bh0, bh1, bh2, bh3, bl0, bl1, bl2, bl3;
                ldsm_x4(bh0, bh1, bh2, bh3, sBh_b + off);
                ldsm_x4(bl0, bl1, bl2, bl3, sBl_b + off);
#pragma unroll
                for (int mt = 0; mt < 2; ++mt) {
                    mma_bf16(acc[mt][2*np],   ah[mt][0],ah[mt][1],ah[mt][2],ah[mt][3], bh0, bh2);
                    mma_bf16(acc[mt][2*np],   ah[mt][0],ah[mt][1],ah[mt][2],ah[mt][3], bl0, bl2);
                    mma_bf16(acc[mt][2*np],   al[mt][0],al[mt][1],al[mt][2],al[mt][3], bh0, bh2);
                    mma_bf16(acc[mt][2*np+1], ah[mt][0],ah[mt][1],ah[mt][2],ah[mt][3], bh1, bh3);
                    mma_bf16(acc[mt][2*np+1], ah[mt][0],ah[mt][1],ah[mt][2],ah[mt][3], bl1, bl3);
                    mma_bf16(acc[mt][2*np+1], al[mt][0],al[mt][1],al[mt][2],al[mt][3], bh1, bh3);
                }
            }
        }
        __syncthreads();
    }

    const int qrow = lane >> 2;
    const int qcol = (lane & 3) * 2;
#pragma unroll
    for (int mt = 0; mt < 2; ++mt) {
        const int r0 = bm + wm * 32 + mt * 16 + qrow;
#pragma unroll
        for (int nt = 0; nt < 4; ++nt) {
            const int c = bn + wn * 32 + nt * 8 + qcol;
            float2 bs = *reinterpret_cast<const float2*>(bias + c);
            float2 v0; v0.x = acc[mt][nt][0] + bs.x; v0.y = acc[mt][nt][1] + bs.y;
            float2 v1; v1.x = acc[mt][nt][2] + bs.x; v1.y = acc[mt][nt][3] + bs.y;
            *reinterpret_cast<float2*>(C + (size_t)r0 * N + c)       = v0;
            *reinterpret_cast<float2*>(C + (size_t)(r0 + 8) * N + c) = v1;
        }
    }
}

// ============================================================================
// Phase 2: persistent recurrence, A operands LDG'd from fragment-ordered h
// (R13-proven; fast split in epilogue, nanosleep(32))
// ============================================================================
#define WH_STRIDE   1032
#define WH_PLANE    (32 * WH_STRIDE * 2)          // 66048 B
#define PBUF_OFF    (2 * WH_PLANE)                 // 132096
#define SMEM2_BYTES (PBUF_OFF + 16 * 1024 * 4)     // 197632

__global__ void __launch_bounds__(BLK2, 1)
rnn_steps_tc(const float* __restrict__ h0, const float* __restrict__ Wh,
             const float* __restrict__ bh, float* __restrict__ out)
{
    extern __shared__ __align__(16) char smem2[];
    __nv_bfloat16* whh = reinterpret_cast<__nv_bfloat16*>(smem2);
    __nv_bfloat16* whl = whh + 32 * WH_STRIDE;
    float* pbuf = reinterpret_cast<float*>(smem2 + PBUF_OFF);

    const int tid  = threadIdx.x;
    const int warp = tid >> 5;
    const int lane = tid & 31;
    const int cgrp = blockIdx.x & 31;
    const int bgrp = blockIdx.x >> 5;
    const int n0   = cgrp * 32;

    // ---- convert this CTA's Wh slice to bf16 hi/lo in SMEM (fast split) ----
    for (int idx = tid; idx < 32 * 256; idx += BLK2) {
        int c  = idx >> 8;
        int kv = idx & 255;
        float4 v = *reinterpret_cast<const float4*>(Wh + (size_t)(n0 + c) * H_ + kv * 4);
        uint2 hi, lo;
        split4_fast(v, hi, lo);
        *reinterpret_cast<uint2*>(whh + c * WH_STRIDE + kv * 4) = hi;
        *reinterpret_cast<uint2*>(whl + c * WH_STRIDE + kv * 4) = lo;
    }

    // ---- convert h0 into fragment-ordered g_ha[0] (disjoint pieces) ----
    {
        int g    = blockIdx.x * 1024 + tid * 2;       // even element index
        int row  = g >> 10;
        int col  = g & 1023;                          // even
        float2 v = *reinterpret_cast<const float2*>(h0 + g);
        u32 ph, pl;
        split2_fast(v.x, v.y, ph, pl);
        int bg = row >> 5, lr = row & 31;
        int ch = col >> 7, c0 = col & 127, q = c0 >> 4, kk = c0 & 15;
        int mt = lr >> 4, rl = lr & 15;
        int j    = (kk >> 3) * 2 + (rl >> 3);
        int lnp  = (rl & 7) * 4 + ((kk & 7) >> 1);
        int slot = ((ch * 8 + q) * 2 + mt) * 128 + lnp * 4 + j;
        g_ha[0][bg][0][slot] = ph;
        g_ha[0][bg][1][slot] = pl;
    }
    __threadfence();
    __syncthreads();
    if (tid == 0) {
        atomicAdd(&g_cnt[511], 1u);
        while (((volatile unsigned*)g_cnt)[511] < NCTA) { __nanosleep(32); }
        __threadfence();
    }
    __syncthreads();

    // ---- per-thread constants ----
    const int myk16 = warp & 7;
    const int chpar = warp >> 3;
    const u32 whh_b = (u32)__cvta_generic_to_shared(whh);
    const u32 whl_b = (u32)__cvta_generic_to_shared(whl);
    const u32 lrow  = lane & 15;
    const u32 lkof  = (lane >> 4) * 16;

    const int afrag0 = (chpar * 8 + myk16) * 2 * 128 + lane * 4;
    const int astep  = 2 * 8 * 2 * 128;

    const int e     = tid;
    const int lrow2 = e >> 4;
    const int lcol2 = (e & 15) * 2;
    const int grow  = bgrp * 32 + lrow2;
    const int gcol  = n0 + lcol2;
    const float2 wb = *reinterpret_cast<const float2*>(bh + gcol);
    const size_t o_off = (size_t)grow * H_ + gcol;

    int ep_slot;
    {
        int ch = gcol >> 7, c0 = gcol & 127, q = c0 >> 4, kk = c0 & 15;
        int mt = lrow2 >> 4, rl = lrow2 & 15;
        int j   = (kk >> 3) * 2 + (rl >> 3);
        int lnp = (rl & 7) * 4 + ((kk & 7) >> 1);
        ep_slot = ((ch * 8 + q) * 2 + mt) * 128 + lnp * 4 + j;
    }

    const int prow  = lane >> 2;
    const int pcol2 = (lane & 3) * 2;

    // xi for step 0
    float2 xi = *reinterpret_cast<const float2*>(out + o_off);

    for (int t = 0; t < L_; ++t) {
        const u32* pAh = g_ha[t & 1][bgrp][0];
        const u32* pAl = g_ha[t & 1][bgrp][1];
        float* ot = out + (size_t)t * B_ * H_;

        float acc[2][4][4];
#pragma unroll
        for (int mt = 0; mt < 2; ++mt)
#pragma unroll
            for (int nt = 0; nt < 4; ++nt)
#pragma unroll
                for (int q = 0; q < 4; ++q) acc[mt][nt][q] = 0.f;

        uint4 cAh0 = *reinterpret_cast<const uint4*>(pAh + afrag0);
        uint4 cAh1 = *reinterpret_cast<const uint4*>(pAh + afrag0 + 128);
        uint4 cAl0 = *reinterpret_cast<const uint4*>(pAl + afrag0);
        uint4 cAl1 = *reinterpret_cast<const uint4*>(pAl + afrag0 + 128);

#pragma unroll
        for (int r = 0; r < 4; ++r) {
            uint4 nAh0, nAh1, nAl0, nAl1;
            if (r < 3) {
                const int na = afrag0 + (r + 1) * astep;
                nAh0 = *reinterpret_cast<const uint4*>(pAh + na);
                nAh1 = *reinterpret_cast<const uint4*>(pAh + na + 128);
                nAl0 = *reinterpret_cast<const uint4*>(pAl + na);
                nAl1 = *reinterpret_cast<const uint4*>(pAl + na + 128);
            }

            const int ch    = 2 * r + chpar;
            const int kglob = ch * 128 + myk16 * 16;
            const u32 ah[2][4] = {{cAh0.x, cAh0.y, cAh0.z, cAh0.w},
                                  {cAh1.x, cAh1.y, cAh1.z, cAh1.w}};
            const u32 al[2][4] = {{cAl0.x, cAl0.y, cAl0.z, cAl0.w},
                                  {cAl1.x, cAl1.y, cAl1.z, cAl1.w}};
#pragma unroll
            for (int np = 0; np < 2; ++np) {
                u32 boff = (np * 16 + lrow) * (WH_STRIDE * 2) + kglob * 2 + lkof;
                u32 bh0, bh1, bh2, bh3, bl0, bl1, bl2, bl3;
                ldsm_x4(bh0, bh1, bh2, bh3, whh_b + boff);
                ldsm_x4(bl0, bl1, bl2, bl3, whl_b + boff);
#pragma unroll
                for (int mt = 0; mt < 2; ++mt) {
                    mma_bf16(acc[mt][2*np],   ah[mt][0],ah[mt][1],ah[mt][2],ah[mt][3], bh0, bh2);
                    mma_bf16(acc[mt][2*np],   ah[mt][0],ah[mt][1],ah[mt][2],ah[mt][3], bl0, bl2);
                    mma_bf16(acc[mt][2*np],   al[mt][0],al[mt][1],al[mt][2],al[mt][3], bh0, bh2);
                    mma_bf16(acc[mt][2*np+1], ah[mt][0],ah[mt][1],ah[mt][2],ah[mt][3], bh1, bh3);
                    mma_bf16(acc[mt][2*np+1], ah[mt][0],ah[mt][1],ah[mt][2],ah[mt][3], bl1, bl3);
                    mma_bf16(acc[mt][2*np+1], al[mt][0],al[mt][1],al[mt][2],al[mt][3], bh1, bh3);
                }
            }
            if (r < 3) { cAh0 = nAh0; cAh1 = nAh1; cAl0 = nAl0; cAl1 = nAl1; }
        }

        // ---- store partials ----
#pragma unroll
        for (int mt = 0; mt < 2; ++mt)
#pragma unroll
            for (int nt = 0; nt < 4; ++nt) {
                int b = warp * 1024 + (mt * 16 + prow) * 32 + nt * 8 + pcol2;
                float2 v0 = {acc[mt][nt][0], acc[mt][nt][1]};
                float2 v1 = {acc[mt][nt][2], acc[mt][nt][3]};
                *reinterpret_cast<float2*>(&pbuf[b])          = v0;
                *reinterpret_cast<float2*>(&pbuf[b + 8 * 32]) = v1;
            }
        __syncthreads();

        // ---- 16-way k-reduction + fused epilogue ----
        ull s2 = *reinterpret_cast<const ull*>(&pbuf[2 * e]);
#pragma unroll
        for (int w = 1; w < 16; ++w)
            s2 = add2(s2, *reinterpret_cast<const ull*>(&pbuf[w * 1024 + 2 * e]));
        float s0, s1;
        unpack2(s0, s1, s2);

        float v0 = tanhf(s0 + wb.x + xi.x);
        float v1 = tanhf(s1 + wb.y + xi.y);
        float2 vv = {v0, v1};
        *reinterpret_cast<float2*>(ot + o_off) = vv;

        // write h_t pair into fragment-ordered carry (fast split)
        u32 ph, pl;
        split2_fast(v0, v1, ph, pl);
        const int nxt = (t + 1) & 1;
        g_ha[nxt][bgrp][0][ep_slot] = ph;
        g_ha[nxt][bgrp][1][ep_slot] = pl;

        if (t < L_ - 1) {
            // prefetch next step's xi (hidden under the barrier spin)
            xi = *reinterpret_cast<const float2*>(ot + B_ * H_ + o_off);

            __threadfence();
            __syncthreads();
            if (tid == 0) {
                atomicAdd(&g_cnt[t], 1u);
                while (((volatile unsigned*)g_cnt)[t] < NCTA) { __nanosleep(32); }
                __threadfence();
            }
            __syncthreads();
        }
    }
}

__global__ void reset_cnt() {
    int i = blockIdx.x * blockDim.x + threadIdx.x;
    if (i < L_) g_cnt[i] = 0;
}

// ---------------- launcher ----------------
extern "C" void kernel_launch(void* const* d_in, const int* in_sizes, int n_in,
                              void* d_out, int out_size)
{
    const float* x    = (const float*)d_in[0];  // [L,B,D]
    const float* h0   = (const float*)d_in[1];  // [B,H]
    const float* Wi_w = (const float*)d_in[2];  // [H,D]
    const float* Wi_b = (const float*)d_in[3];  // [H]
    const float* Wh_w = (const float*)d_in[4];  // [H,H]
    const float* Wh_b = (const float*)d_in[5];  // [H]
    float* out = (float*)d_out;                 // [L,B,H]

    // Phase 1: out = x @ Wi^T + bi  (tensor cores, bf16 split, 2 CTAs/SM)
    {
        const int M1 = L_ * B_;
        dim3 grid(H_ / P1_BN, M1 / P1_BM);
        gemm_bf16split<<<grid, 256>>>(x, Wi_w, Wi_b, out, M1, H_, H_);
    }

    // Phase 2: persistent tensor-core recurrence
    {
        cudaFuncSetAttribute(rnn_steps_tc, cudaFuncAttributeMaxDynamicSharedMemorySize,
                             SMEM2_BYTES);
        rnn_steps_tc<<<NCTA, BLK2, SMEM2_BYTES>>>(h0, Wh_w, Wh_b, out);
    }

    // Phase 3: reset barrier counters for the next graph replay
    reset_cnt<<<(L_ + 255) / 256, 256>>>();
}

// round 17
// speedup vs baseline: 1.3145x; 1.0591x over previous
#include <cuda_runtime.h>
#include <cuda_bf16.h>
#include <math.h>

// ============================================================================
// RNN: h_t = tanh(x_t @ Wi^T + bi + h_{t-1} @ Wh^T + bh)
// Phase 1: bf16 hi/lo split mma.sync GEMM (128x64 tile, 2 CTAs/SM, fast
//          truncation split) -- R15-identical (proven).
// Phase 2: persistent tensor-core recurrence, now 256 CTAs x 256 threads
//          (2 CTAs/SM): each CTA owns 32 batch-rows x 16 cols. Co-resident
//          CTAs overlap each other's reduction/epilogue/barrier tails on the
//          tensor pipe. 8-way k-split (warp = k16 lane, marches 8 chunks),
//          8-way reduction. Sync idiom byte-identical to R15 (proven):
//          atomic counter + all-thread fences + nanosleep(32).
// NOTE: tcgen05 unusable here (harness targets compute_100 virtual arch).
// Shapes hardcoded: L=512, B=128, D=H=1024 (fp32).
// ============================================================================

#define L_    512
#define B_    128
#define H_    1024
#define NCTA2 256                 // phase-2 grid (2 CTAs/SM)
#define BLK3  256                 // phase-2 threads per CTA (8 warps)

typedef unsigned long long ull;
typedef unsigned int u32;

__device__ unsigned g_cnt[L_];   // 0..510 step barriers, 511 pre-barrier

// h carry in MMA-fragment order (layout unchanged from R12..R15):
//   g_ha[pingpong][bgrp][plane(0=hi,1=lo)][16384 u32]
//   slot for (ch, q, mt), lane, j:  ((ch*8+q)*2+mt)*128 + lane*4 + j
__device__ __align__(128) u32 g_ha[2][4][2][16384];

// ---------------- small helpers ----------------
__device__ __forceinline__ void unpack2(float& lo, float& hi, ull v) {
    unsigned a, b;
    asm("mov.b64 {%0, %1}, %2;" : "=r"(a), "=r"(b) : "l"(v));
    lo = __uint_as_float(a); hi = __uint_as_float(b);
}
__device__ __forceinline__ ull add2(ull a, ull b) {
    ull d;
    asm("add.rn.f32x2 %0, %1, %2;" : "=l"(d) : "l"(a), "l"(b));
    return d;
}
__device__ __forceinline__ void ldsm_x4(u32& r0, u32& r1, u32& r2, u32& r3, u32 addr) {
    asm volatile("ldmatrix.sync.aligned.m8n8.x4.shared.b16 {%0,%1,%2,%3}, [%4];"
                 : "=r"(r0), "=r"(r1), "=r"(r2), "=r"(r3) : "r"(addr));
}
__device__ __forceinline__ void mma_bf16(float* c, u32 a0, u32 a1, u32 a2, u32 a3,
                                         u32 b0, u32 b1) {
    asm volatile("mma.sync.aligned.m16n8k16.row.col.f32.bf16.bf16.f32 "
                 "{%0,%1,%2,%3}, {%4,%5,%6,%7}, {%8,%9}, {%0,%1,%2,%3};"
                 : "+f"(c[0]), "+f"(c[1]), "+f"(c[2]), "+f"(c[3])
                 : "r"(a0), "r"(a1), "r"(a2), "r"(a3), "r"(b0), "r"(b1));
}
// FAST truncation split: hi = top16(v), lo = rn_bf16(v - hi).
__device__ __forceinline__ u32 cvt2bf16(float hi_lane, float lo_lane) {
    u32 r;
    asm("cvt.rn.bf16x2.f32 %0, %1, %2;" : "=r"(r) : "f"(hi_lane), "f"(lo_lane));
    return r;
}
__device__ __forceinline__ void split4_fast(float4 v, uint2& hi, uint2& lo) {
    u32 x0 = __float_as_uint(v.x), x1 = __float_as_uint(v.y);
    u32 x2 = __float_as_uint(v.z), x3 = __float_as_uint(v.w);
    hi.x = __byte_perm(x0, x1, 0x7632);
    hi.y = __byte_perm(x2, x3, 0x7632);
    float l0 = v.x - __uint_as_float(x0 & 0xFFFF0000u);
    float l1 = v.y - __uint_as_float(x1 & 0xFFFF0000u);
    float l2 = v.z - __uint_as_float(x2 & 0xFFFF0000u);
    float l3 = v.w - __uint_as_float(x3 & 0xFFFF0000u);
    lo.x = cvt2bf16(l1, l0);
    lo.y = cvt2bf16(l3, l2);
}
__device__ __forceinline__ void split2_fast(float v0, float v1, u32& hi, u32& lo) {
    u32 b0 = __float_as_uint(v0), b1 = __float_as_uint(v1);
    hi = __byte_perm(b0, b1, 0x7632);
    float l0 = v0 - __uint_as_float(b0 & 0xFFFF0000u);
    float l1 = v1 - __uint_as_float(b1 & 0xFFFF0000u);
    lo = cvt2bf16(l1, l0);
}

// ============================================================================
// Phase 1: bf16-split tensor-core GEMM, 128x64 tile, 2 CTAs/SM (R15-identical)
// ============================================================================
#define P1_BM 128
#define P1_BN 64
#define P1_BK 32
#define LDS_  40

__global__ void __launch_bounds__(256, 2)
gemm_bf16split(const float* __restrict__ A, const float* __restrict__ B,
               const float* __restrict__ bias, float* __restrict__ C,
               int M, int N, int K)
{
    __shared__ __align__(16) __nv_bfloat16 sAh[P1_BM * LDS_];
    __shared__ __align__(16) __nv_bfloat16 sAl[P1_BM * LDS_];
    __shared__ __align__(16) __nv_bfloat16 sBh[P1_BN * LDS_];
    __shared__ __align__(16) __nv_bfloat16 sBl[P1_BN * LDS_];

    const int tid  = threadIdx.x;
    const int warp = tid >> 5;
    const int lane = tid & 31;
    const int wm   = warp & 3;
    const int wn   = warp >> 2;
    const int bm   = blockIdx.y * P1_BM;
    const int bn   = blockIdx.x * P1_BN;

    const float* agp[4];
    int arow[4], ac4[4];
#pragma unroll
    for (int i = 0; i < 4; ++i) {
        int f = tid + i * 256;
        arow[i] = f >> 3; ac4[i] = f & 7;
        agp[i] = A + (size_t)(bm + arow[i]) * K + ac4[i] * 4;
    }
    const float* bgp[2];
    int brow[2], bc4[2];
#pragma unroll
    for (int i = 0; i < 2; ++i) {
        int f = tid + i * 256;
        brow[i] = f >> 3; bc4[i] = f & 7;
        bgp[i] = B + (size_t)(bn + brow[i]) * K + bc4[i] * 4;
    }

    const u32 lrow = lane & 15;
    const u32 lkof = (lane >> 4) * 16;
    const u32 aoff0 = (wm * 32 + lrow) * (LDS_ * 2) + lkof;
    const u32 boff0 = (wn * 32 + lrow) * (LDS_ * 2) + lkof;
    const u32 sAh_b = (u32)__cvta_generic_to_shared(sAh);
    const u32 sAl_b = (u32)__cvta_generic_to_shared(sAl);
    const u32 sBh_b = (u32)__cvta_generic_to_shared(sBh);
    const u32 sBl_b = (u32)__cvta_generic_to_shared(sBl);

    float acc[2][4][4];
#pragma unroll
    for (int mt = 0; mt < 2; ++mt)
#pragma unroll
        for (int nt = 0; nt < 4; ++nt)
#pragma unroll
            for (int q = 0; q < 4; ++q) acc[mt][nt][q] = 0.f;

    float4 pa[4], pb[2];
#pragma unroll
    for (int i = 0; i < 4; ++i) pa[i] = *reinterpret_cast<const float4*>(agp[i]);
#pragma unroll
    for (int i = 0; i < 2; ++i) pb[i] = *reinterpret_cast<const float4*>(bgp[i]);

    const int NKT = K / P1_BK;
    for (int kt = 0; kt < NKT; ++kt) {
#pragma unroll
        for (int i = 0; i < 4; ++i) {
            uint2 hi, lo;
            int e = arow[i] * LDS_ + ac4[i] * 4;
            split4_fast(pa[i], hi, lo);
            *reinterpret_cast<uint2*>(&sAh[e]) = hi;
            *reinterpret_cast<uint2*>(&sAl[e]) = lo;
        }
#pragma unroll
        for (int i = 0; i < 2; ++i) {
            uint2 hi, lo;
            int e = brow[i] * LDS_ + bc4[i] * 4;
            split4_fast(pb[i], hi, lo);
            *reinterpret_cast<uint2*>(&sBh[e]) = hi;
            *reinterpret_cast<uint2*>(&sBl[e]) = lo;
        }
        __syncthreads();

        if (kt + 1 < NKT) {
#pragma unroll
            for (int i = 0; i < 4; ++i)
                pa[i] = *reinterpret_cast<const float4*>(agp[i] + (kt + 1) * P1_BK);
#pragma unroll
            for (int i = 0; i < 2; ++i)
                pb[i] = *reinterpret_cast<const float4*>(bgp[i] + (kt + 1) * P1_BK);
        }

#pragma unroll
        for (int ks = 0; ks < 2; ++ks) {
            const u32 kb = ks * 32;
            u32 ah[2][4], al[2][4];
#pragma unroll
            for (int mt = 0; mt < 2; ++mt) {
                u32 off = aoff0 + mt * 16 * (LDS_ * 2) + kb;
                ldsm_x4(ah[mt][0], ah[mt][1], ah[mt][2], ah[mt][3], sAh_b + off);
                ldsm_x4(al[mt][0], al[mt][1], al[mt][2], al[mt][3], sAl_b + off);
            }
#pragma unroll
            for (int np = 0; np < 2; ++np) {
                u32 off = boff0 + np * 16 * (LDS_ * 2) + kb;
                u32 bh0, bh1, bh2, bh3, bl0, bl1, bl2, bl3;
                ldsm_x4(bh0, bh1, bh2, bh3, sBh_b + off);
                ldsm_x4(bl0, bl1, bl2, bl3, sBl_b + off);
#pragma unroll
                for (int mt = 0; mt < 2; ++mt) {
                    mma_bf16(acc[mt][2*np],   ah[mt][0],ah[mt][1],ah[mt][2],ah[mt][3], bh0, bh2);
                    mma_bf16(acc[mt][2*np],   ah[mt][0],ah[mt][1],ah[mt][2],ah[mt][3], bl0, bl2);
                    mma_bf16(acc[mt][2*np],   al[mt][0],al[mt][1],al[mt][2],al[mt][3], bh0, bh2);
                    mma_bf16(acc[mt][2*np+1], ah[mt][0],ah[mt][1],ah[mt][2],ah[mt][3], bh1, bh3);
                    mma_bf16(acc[mt][2*np+1], ah[mt][0],ah[mt][1],ah[mt][2],ah[mt][3], bl1, bl3);
                    mma_bf16(acc[mt][2*np+1], al[mt][0],al[mt][1],al[mt][2],al[mt][3], bh1, bh3);
                }
            }
        }
        __syncthreads();
    }

    const int qrow = lane >> 2;
    const int qcol = (lane & 3) * 2;
#pragma unroll
    for (int mt = 0; mt < 2; ++mt) {
        const int r0 = bm + wm * 32 + mt * 16 + qrow;
#pragma unroll
        for (int nt = 0; nt < 4; ++nt) {
            const int c = bn + wn * 32 + nt * 8 + qcol;
            float2 bs = *reinterpret_cast<const float2*>(bias + c);
            float2 v0; v0.x = acc[mt][nt][0] + bs.x; v0.y = acc[mt][nt][1] + bs.y;
            float2 v1; v1.x = acc[mt][nt][2] + bs.x; v1.y = acc[mt][nt][3] + bs.y;
            *reinterpret_cast<float2*>(C + (size_t)r0 * N + c)       = v0;
            *reinterpret_cast<float2*>(C + (size_t)(r0 + 8) * N + c) = v1;
        }
    }
}

// ============================================================================
// Phase 2: persistent recurrence, 256 CTAs x 256 thr (2/SM), 32r x 16c per CTA
// SMEM: Wh hi/lo [16][1032] bf16 (66KB) + pbuf [8][512] fp32 (16KB)
// ============================================================================
#define WH_STRIDE   1032
#define WH_PLANE16  (16 * WH_STRIDE * 2)          // 33024 B
#define PBUF_OFF    (2 * WH_PLANE16)               // 66048
#define SMEM2_BYTES (PBUF_OFF + 8 * 512 * 4)       // 82432

__global__ void __launch_bounds__(BLK3, 2)
rnn_steps_tc(const float* __restrict__ h0, const float* __restrict__ Wh,
             const float* __restrict__ bh, float* __restrict__ out)
{
    extern __shared__ __align__(16) char smem2[];
    __nv_bfloat16* whh = reinterpret_cast<__nv_bfloat16*>(smem2);
    __nv_bfloat16* whl = whh + 16 * WH_STRIDE;
    float* pbuf = reinterpret_cast<float*>(smem2 + PBUF_OFF);

    const int tid  = threadIdx.x;
    const int warp = tid >> 5;          // 0..7 = k16 lane q
    const int lane = tid & 31;
    const int cgrp = blockIdx.x & 63;   // 64 col groups of 16
    const int bgrp = blockIdx.x >> 6;   // 4 batch groups of 32 rows
    const int n0   = cgrp * 16;

    // ---- convert this CTA's Wh slice (16 cols) to bf16 hi/lo in SMEM ----
    for (int idx = tid; idx < 16 * 256; idx += BLK3) {
        int c  = idx >> 8;
        int kv = idx & 255;
        float4 v = *reinterpret_cast<const float4*>(Wh + (size_t)(n0 + c) * H_ + kv * 4);
        uint2 hi, lo;
        split4_fast(v, hi, lo);
        *reinterpret_cast<uint2*>(whh + c * WH_STRIDE + kv * 4) = hi;
        *reinterpret_cast<uint2*>(whl + c * WH_STRIDE + kv * 4) = lo;
    }

    // ---- convert h0 into fragment-ordered g_ha[0] (disjoint pieces) ----
    {
        int g    = blockIdx.x * 512 + tid * 2;        // even element index
        int row  = g >> 10;
        int col  = g & 1023;                          // even
        float2 v = *reinterpret_cast<const float2*>(h0 + g);
        u32 ph, pl;
        split2_fast(v.x, v.y, ph, pl);
        int bg = row >> 5, lr = row & 31;
        int ch = col >> 7, c0 = col & 127, q = c0 >> 4, kk = c0 & 15;
        int mt = lr >> 4, rl = lr & 15;
        int j    = (kk >> 3) * 2 + (rl >> 3);
        int lnp  = (rl & 7) * 4 + ((kk & 7) >> 1);
        int slot = ((ch * 8 + q) * 2 + mt) * 128 + lnp * 4 + j;
        g_ha[0][bg][0][slot] = ph;
        g_ha[0][bg][1][slot] = pl;
    }
    __threadfence();
    __syncthreads();
    if (tid == 0) {
        atomicAdd(&g_cnt[511], 1u);
        while (((volatile unsigned*)g_cnt)[511] < NCTA2) { __nanosleep(32); }
        __threadfence();
    }
    __syncthreads();

    // ---- per-thread constants ----
    const u32 whh_b = (u32)__cvta_generic_to_shared(whh);
    const u32 whl_b = (u32)__cvta_generic_to_shared(whl);
    const u32 lrow  = lane & 15;
    const u32 lkof  = (lane >> 4) * 16;

    // A-fragment slot (ch=0, q=warp): ((0*8+warp)*2)*128 + lane*4; mt at +128
    const int afrag0 = warp * 2 * 128 + lane * 4;
    const int astep  = 8 * 2 * 128;                  // +1 chunk = 2048 u32

    // reduction / epilogue mapping: thread e owns local elems (2e, 2e+1)
    const int e     = tid;
    const int lrow2 = e >> 3;                        // 0..31
    const int lcol2 = (e & 7) * 2;                   // 0..14 even
    const int grow  = bgrp * 32 + lrow2;
    const int gcol  = n0 + lcol2;
    const float2 wb = *reinterpret_cast<const float2*>(bh + gcol);
    const size_t o_off = (size_t)grow * H_ + gcol;

    int ep_slot;
    {
        int ch = gcol >> 7, c0 = gcol & 127, q = c0 >> 4, kk = c0 & 15;
        int mt = lrow2 >> 4, rl = lrow2 & 15;
        int j   = (kk >> 3) * 2 + (rl >> 3);
        int lnp = (rl & 7) * 4 + ((kk & 7) >> 1);
        ep_slot = ((ch * 8 + q) * 2 + mt) * 128 + lnp * 4 + j;
    }

    const int prow  = lane >> 2;
    const int pcol2 = (lane & 3) * 2;

    // xi for step 0
    float2 xi = *reinterpret_cast<const float2*>(out + o_off);

    for (int t = 0; t < L_; ++t) {
        const u32* pAh = g_ha[t & 1][bgrp][0];
        const u32* pAl = g_ha[t & 1][bgrp][1];
        float* ot = out + (size_t)t * B_ * H_;

        float acc[2][2][4];
#pragma unroll
        for (int mt = 0; mt < 2; ++mt)
#pragma unroll
            for (int nt = 0; nt < 2; ++nt)
#pragma unroll
                for (int q = 0; q < 4; ++q) acc[mt][nt][q] = 0.f;

        // prefetch chunk 0 A fragments
        uint4 cAh0 = *reinterpret_cast<const uint4*>(pAh + afrag0);
        uint4 cAh1 = *reinterpret_cast<const uint4*>(pAh + afrag0 + 128);
        uint4 cAl0 = *reinterpret_cast<const uint4*>(pAl + afrag0);
        uint4 cAl1 = *reinterpret_cast<const uint4*>(pAl + afrag0 + 128);

#pragma unroll
        for (int r = 0; r < 8; ++r) {                // r = chunk
            uint4 nAh0, nAh1, nAl0, nAl1;
            if (r < 7) {
                const int na = afrag0 + (r + 1) * astep;
                nAh0 = *reinterpret_cast<const uint4*>(pAh + na);
                nAh1 = *reinterpret_cast<const uint4*>(pAh + na + 128);
                nAl0 = *reinterpret_cast<const uint4*>(pAl + na);
                nAl1 = *reinterpret_cast<const uint4*>(pAl + na + 128);
            }

            const int kglob = r * 128 + warp * 16;
            const u32 ah[2][4] = {{cAh0.x, cAh0.y, cAh0.z, cAh0.w},
                                  {cAh1.x, cAh1.y, cAh1.z, cAh1.w}};
            const u32 al[2][4] = {{cAl0.x, cAl0.y, cAl0.z, cAl0.w},
                                  {cAl1.x, cAl1.y, cAl1.z, cAl1.w}};

            // B: single n16k16 fragment per plane (16 cols total)
            u32 boff = lrow * (WH_STRIDE * 2) + kglob * 2 + lkof;
            u32 bh0, bh1, bh2, bh3, bl0, bl1, bl2, bl3;
            ldsm_x4(bh0, bh1, bh2, bh3, whh_b + boff);
            ldsm_x4(bl0, bl1, bl2, bl3, whl_b + boff);
#pragma unroll
            for (int mt = 0; mt < 2; ++mt) {
                mma_bf16(acc[mt][0], ah[mt][0],ah[mt][1],ah[mt][2],ah[mt][3], bh0, bh2);
                mma_bf16(acc[mt][0], ah[mt][0],ah[mt][1],ah[mt][2],ah[mt][3], bl0, bl2);
                mma_bf16(acc[mt][0], al[mt][0],al[mt][1],al[mt][2],al[mt][3], bh0, bh2);
                mma_bf16(acc[mt][1], ah[mt][0],ah[mt][1],ah[mt][2],ah[mt][3], bh1, bh3);
                mma_bf16(acc[mt][1], ah[mt][0],ah[mt][1],ah[mt][2],ah[mt][3], bl1, bl3);
                mma_bf16(acc[mt][1], al[mt][0],al[mt][1],al[mt][2],al[mt][3], bh1, bh3);
            }
            if (r < 7) { cAh0 = nAh0; cAh1 = nAh1; cAl0 = nAl0; cAl1 = nAl1; }
        }

        // ---- store partials: warp tile 32 rows x 16 cols at pbuf[warp*512] ----
#pragma unroll
        for (int mt = 0; mt < 2; ++mt)
#pragma unroll
            for (int nt = 0; nt < 2; ++nt) {
                int b = warp * 512 + (mt * 16 + prow) * 16 + nt * 8 + pcol2;
                float2 v0 = {acc[mt][nt][0], acc[mt][nt][1]};
                float2 v1 = {acc[mt][nt][2], acc[mt][nt][3]};
                *reinterpret_cast<float2*>(&pbuf[b])       = v0;
                *reinterpret_cast<float2*>(&pbuf[b + 128]) = v1;   // row +8
            }
        __syncthreads();

        // ---- 8-way k-reduction + fused epilogue ----
        ull s2 = *reinterpret_cast<const ull*>(&pbuf[2 * e]);
#pragma unroll
        for (int w = 1; w < 8; ++w)
            s2 = add2(s2, *reinterpret_cast<const ull*>(&pbuf[w * 512 + 2 * e]));
        float s0, s1;
        unpack2(s0, s1, s2);

        float v0 = tanhf(s0 + wb.x + xi.x);
        float v1 = tanhf(s1 + wb.y + xi.y);
        float2 vv = {v0, v1};
        *reinterpret_cast<float2*>(ot + o_off) = vv;

        // write h_t pair into fragment-ordered carry (fast split)
        u32 ph, pl;
        split2_fast(v0, v1, ph, pl);
        const int nxt = (t + 1) & 1;
        g_ha[nxt][bgrp][0][ep_slot] = ph;
        g_ha[nxt][bgrp][1][ep_slot] = pl;

        if (t < L_ - 1) {
            // prefetch next step's xi (hidden under the barrier spin)
            xi = *reinterpret_cast<const float2*>(ot + B_ * H_ + o_off);

            __threadfence();
            __syncthreads();
            if (tid == 0) {
                atomicAdd(&g_cnt[t], 1u);
                while (((volatile unsigned*)g_cnt)[t] < NCTA2) { __nanosleep(32); }
                __threadfence();
            }
            __syncthreads();
        }
    }
}

__global__ void reset_cnt() {
    int i = blockIdx.x * blockDim.x + threadIdx.x;
    if (i < L_) g_cnt[i] = 0;
}

// ---------------- launcher ----------------
extern "C" void kernel_launch(void* const* d_in, const int* in_sizes, int n_in,
                              void* d_out, int out_size)
{
    const float* x    = (const float*)d_in[0];  // [L,B,D]
    const float* h0   = (const float*)d_in[1];  // [B,H]
    const float* Wi_w = (const float*)d_in[2];  // [H,D]
    const float* Wi_b = (const float*)d_in[3];  // [H]
    const float* Wh_w = (const float*)d_in[4];  // [H,H]
    const float* Wh_b = (const float*)d_in[5];  // [H]
    float* out = (float*)d_out;                 // [L,B,H]

    // Phase 1: out = x @ Wi^T + bi  (tensor cores, bf16 split, 2 CTAs/SM)
    {
        const int M1 = L_ * B_;
        dim3 grid(H_ / P1_BN, M1 / P1_BM);
        gemm_bf16split<<<grid, 256>>>(x, Wi_w, Wi_b, out, M1, H_, H_);
    }

    // Phase 2: persistent tensor-core recurrence (256 CTAs, 2/SM)
    {
        cudaFuncSetAttribute(rnn_steps_tc, cudaFuncAttributeMaxDynamicSharedMemorySize,
                             SMEM2_BYTES);
        rnn_steps_tc<<<NCTA2, BLK3, SMEM2_BYTES>>>(h0, Wh_w, Wh_b, out);
    }

    // Phase 3: reset barrier counters for the next graph replay
    reset_cnt<<<(L_ + 255) / 256, 256>>>();
}